// round 11
// baseline (speedup 1.0000x reference)
#include <cuda_runtime.h>
#include <cuda_fp16.h>
#include <cstdint>

#define NTOK   49
#define NHD    8
#define HDIM   32
#define DMODEL 256
#define NBATCH 4096
#define NWIN   64
#define MROWS  (NBATCH * NTOK)   // 200704

// fp16 scratch. +2048 halves padding: attn loads 64 padded rows per (b,h).
__device__ __half g_q[(size_t)NBATCH * NHD * NTOK * HDIM + 2048];
__device__ __half g_k[(size_t)NBATCH * NHD * NTOK * HDIM + 2048];
__device__ __half g_v[(size_t)NBATCH * NHD * NTOK * HDIM + 2048];
__device__ __half g_w[3 * 256 * 256];           // [mat][n][k] (W transposed)
__device__ float  g_bm[NWIN * NHD * 64 * 68];   // combined mask+bias, 68-f rows

__device__ __forceinline__ void mma16816(float c[4],
                                         uint32_t a0, uint32_t a1, uint32_t a2, uint32_t a3,
                                         uint32_t b0, uint32_t b1) {
    asm volatile(
        "mma.sync.aligned.m16n8k16.row.col.f32.f16.f16.f32 "
        "{%0,%1,%2,%3}, {%4,%5,%6,%7}, {%8,%9}, {%0,%1,%2,%3};"
        : "+f"(c[0]), "+f"(c[1]), "+f"(c[2]), "+f"(c[3])
        : "r"(a0), "r"(a1), "r"(a2), "r"(a3), "r"(b0), "r"(b1));
}

__device__ __forceinline__ void ldsm4(uint32_t r[4], const void* p) {
    uint32_t a = (uint32_t)__cvta_generic_to_shared(p);
    asm volatile("ldmatrix.sync.aligned.m8n8.x4.shared.b16 {%0,%1,%2,%3}, [%4];"
                 : "=r"(r[0]), "=r"(r[1]), "=r"(r[2]), "=r"(r[3]) : "r"(a));
}

__device__ __forceinline__ void ldsm4t(uint32_t r[4], const void* p) {
    uint32_t a = (uint32_t)__cvta_generic_to_shared(p);
    asm volatile("ldmatrix.sync.aligned.m8n8.x4.trans.shared.b16 {%0,%1,%2,%3}, [%4];"
                 : "=r"(r[0]), "=r"(r[1]), "=r"(r[2]), "=r"(r[3]) : "r"(a));
}

__device__ __forceinline__ void cp16(void* s, const void* g) {
    uint32_t sa = (uint32_t)__cvta_generic_to_shared(s);
    asm volatile("cp.async.cg.shared.global [%0], [%1], 16;" :: "r"(sa), "l"(g));
}

__device__ __forceinline__ uint32_t packh2(float x, float y) {
    __half2 h = __floats2half2_rn(x, y);
    return *(uint32_t*)&h;
}

// ---------------------------------------------------------------------------
// prep (measured 13.7us): W transpose+convert + combined bias/mask.
// blocks 0..511 -> bm (w=id>>3, h=id&7); 512..1279 -> W (mat, k).
// ---------------------------------------------------------------------------
__global__ __launch_bounds__(256) void prep(
    const float* __restrict__ mask, const float* __restrict__ table,
    const float* __restrict__ wq, const float* __restrict__ wk,
    const float* __restrict__ wv)
{
    const int id = blockIdx.x;
    if (id < 512) {
        const int w = id >> 3, h = id & 7;
        float* dst = g_bm + ((size_t)(w * NHD + h)) * 64 * 68;
        for (int idx = threadIdx.x; idx < 64 * 68; idx += 256) {
            int i = idx / 68, j = idx - i * 68;
            float v;
            if (j >= NTOK)      v = -1e30f;
            else if (i >= NTOK) v = 0.f;
            else {
                int ih = i / 7, iw = i - ih * 7;
                int jh = j / 7, jw = j - jh * 7;
                int r = (ih - jh + 6) * 13 + (iw - jw + 6);
                v = mask[((size_t)w * NTOK + i) * NTOK + j] + table[r * NHD + h];
            }
            dst[idx] = v;
        }
    } else {
        const int wid = id - 512;
        const int mat = wid >> 8, k = wid & 255, n = threadIdx.x;
        const float* W = (mat == 0) ? wq : (mat == 1) ? wk : wv;
        g_w[((size_t)mat * 256 + n) * 256 + k] = __float2half_rn(W[k * 256 + n]);
    }
}

// ---------------------------------------------------------------------------
// Kernel A: QKV projection with register-staged fp32->fp16 X conversion.
// Structure = round-9 (BM=128, BN=128, BK=64, 2-stage, one top sync + one
// pre-refill sync), but A panels arrive as fp32 LDGs into registers TWO
// panels ahead, converted + STS'd into the idle A16 buffer at the top of
// each iteration. No g_x, no convert_x kernel, no extra staging buffer.
// smem 73728 -> 2 CTAs/SM. grid (6, 1568), bx fastest: 6 CTAs share X via L2.
// ---------------------------------------------------------------------------
#define QKV_SMEM 73728

__global__ __launch_bounds__(256, 2) void qkv_kernel(
    const float* __restrict__ X,
    const float* __restrict__ bq, const float* __restrict__ bk,
    const float* __restrict__ bv)
{
    extern __shared__ __half sm[];   // stage s: A16 at s*18432, B at +9216 (halves)

    const int bx = blockIdx.x, by = blockIdx.y;
    const int tid = threadIdx.x;
    const int warp = tid >> 5, lane = tid & 31;
    const int wm = warp & 1, wn = warp >> 1;
    const int g = lane >> 2, tig = lane & 3;

    const int mat   = bx >> 1;
    const int ncol0 = (bx & 1) * 128;
    const float* bias = (mat == 0) ? bq : (mat == 1) ? bk : bv;

    const float*  xbase = X + (size_t)by * 128 * 256;
    const __half* wbase = g_w + ((size_t)mat * 256 + ncol0) * 256;

    // B tile (fp16 weights, L2-hot) via cp.async, double buffered.
    auto loadB = [&](int s, int kp) {
        __half* B = sm + s * 18432 + 9216;
        const __half* ws = wbase + kp * 64;
#pragma unroll
        for (int c = tid; c < 1024; c += 256) {
            int r = c >> 3, off = (c & 7) * 8;
            cp16(B + r * 72 + off, ws + (size_t)r * 256 + off);
        }
        asm volatile("cp.async.commit_group;" ::: "memory");
    };

    // X panel (128 x 64 fp32): 8 float4 per thread, coalesced 32B/thread.
    float4 xr[4][2];
    auto loadX = [&](int kp) {
#pragma unroll
        for (int j = 0; j < 4; j++) {
            int c2 = tid + j * 256;
            int r = c2 >> 3, c8 = (c2 & 7) * 8;
            const float* p = xbase + (size_t)r * 256 + kp * 64 + c8;
            xr[j][0] = *(const float4*)p;
            xr[j][1] = *(const float4*)(p + 4);
        }
    };
    // Convert + store into A16 stage s (ldsm layout, 72-half rows).
    auto stsX = [&](int s) {
        __half* A = sm + s * 18432;
#pragma unroll
        for (int j = 0; j < 4; j++) {
            int c2 = tid + j * 256;
            int r = c2 >> 3, c8 = (c2 & 7) * 8;
            __half2 h0 = __floats2half2_rn(xr[j][0].x, xr[j][0].y);
            __half2 h1 = __floats2half2_rn(xr[j][0].z, xr[j][0].w);
            __half2 h2 = __floats2half2_rn(xr[j][1].x, xr[j][1].y);
            __half2 h3 = __floats2half2_rn(xr[j][1].z, xr[j][1].w);
            uint4 pk = make_uint4(*(uint32_t*)&h0, *(uint32_t*)&h1,
                                  *(uint32_t*)&h2, *(uint32_t*)&h3);
            *(uint4*)(A + r * 72 + c8) = pk;   // 144r+16k: 16B-aligned
        }
    };

    // Prologue: A16[0] filled directly; B0, B1 in flight; X(1) in registers.
    loadX(0);
    loadB(0, 0);
    loadB(1, 1);
    stsX(0);
    loadX(1);

    float acc[4][4][4];
#pragma unroll
    for (int mt = 0; mt < 4; mt++)
#pragma unroll
        for (int nt = 0; nt < 4; nt++)
#pragma unroll
            for (int e = 0; e < 4; e++) acc[mt][nt][e] = 0.f;

    const int aRow = wm * 64 + (lane & 15);
    const int aCol = (lane & 16) >> 1;
    const int bRow = wn * 32 + (lane & 7) + ((lane & 16) >> 1);
    const int bCol = lane & 8;

#pragma unroll
    for (int kp = 0; kp < 4; kp++) {
        if (kp < 3) asm volatile("cp.async.wait_group 1;" ::: "memory");
        else        asm volatile("cp.async.wait_group 0;" ::: "memory");
        __syncthreads();   // B(kp) resident; A16 stores from prev iter visible

        // Stage next A panel into the other buffer; prefetch X two ahead.
        if (kp < 3) stsX((kp + 1) & 1);
        if (kp < 2) loadX(kp + 2);

        const __half* A = sm + (kp & 1) * 18432;
        const __half* B = sm + (kp & 1) * 18432 + 9216;

#pragma unroll
        for (int ks = 0; ks < 4; ks++) {
            const int kc = ks * 16;
            uint32_t bf0[4], bf1[4];
            ldsm4(bf0, B + bRow * 72 + kc + bCol);
            ldsm4(bf1, B + (bRow + 16) * 72 + kc + bCol);
#pragma unroll
            for (int mt = 0; mt < 4; mt++) {
                uint32_t a[4];
                ldsm4(a, A + (aRow + mt * 16) * 72 + kc + aCol);
                mma16816(acc[mt][0], a[0], a[1], a[2], a[3], bf0[0], bf0[1]);
                mma16816(acc[mt][1], a[0], a[1], a[2], a[3], bf0[2], bf0[3]);
                mma16816(acc[mt][2], a[0], a[1], a[2], a[3], bf1[0], bf1[1]);
                mma16816(acc[mt][3], a[0], a[1], a[2], a[3], bf1[2], bf1[3]);
            }
        }

        if (kp < 2) {
            __syncthreads();           // B(kp) reads done before refill
            loadB(kp & 1, kp + 2);
        }
    }

    __half* outp = (mat == 0) ? g_q : (mat == 1) ? g_k : g_v;
    const float scale = (mat == 0) ? 0.17677669529663687f : 1.0f;
#pragma unroll
    for (int mt = 0; mt < 4; mt++) {
#pragma unroll
        for (int hf = 0; hf < 2; hf++) {
            int m = by * 128 + wm * 64 + mt * 16 + g + hf * 8;
            int b = m / NTOK, n = m - b * NTOK;
#pragma unroll
            for (int nt = 0; nt < 4; nt++) {
                int c = ncol0 + wn * 32 + nt * 8 + 2 * tig;
                int h = c >> 5, d = c & 31;
                float v0 = (acc[mt][nt][hf * 2 + 0] + bias[c]) * scale;
                float v1 = (acc[mt][nt][hf * 2 + 1] + bias[c + 1]) * scale;
                *(__half2*)(outp + ((((size_t)b * NHD + h) * NTOK + n) * HDIM + d)) =
                    __floats2half2_rn(v0, v1);
            }
        }
    }
}

// ---------------------------------------------------------------------------
// Kernel B: windowed attention (frozen from round 9 — measured optimum).
// Two windows per CTA sharing one bm tile; P stays in registers.
// ---------------------------------------------------------------------------
#define WINBUF 15360   // Qs 5120 + Ks 5120 + Vs 5120

__global__ __launch_bounds__(256, 3) void attn_kernel(float* __restrict__ out)
{
    __shared__ alignas(128) char smraw[2 * WINBUF + 17408];

    const int b0 = blockIdx.x;          // 0..2047
    const int h  = blockIdx.y;
    const int w  = b0 & (NWIN - 1);

    const int tid = threadIdx.x;
    const int warp = tid >> 5, lane = tid & 31;
    const int half = warp >> 2;
    const int wl   = warp & 3;
    const int ht   = tid & 127;
    const int g = lane >> 2, tig = lane & 3;
    const int m0 = wl * 16;

    const int b = b0 + half * 2048;

    char* hb = smraw + half * WINBUF;
    __half (*Qs)[40] = (__half(*)[40])(hb);
    __half (*Ks)[40] = (__half(*)[40])(hb + 5120);
    __half (*Vs)[40] = (__half(*)[40])(hb + 10240);
    float* bmS = (float*)(smraw + 2 * WINBUF);
    float* Os  = (float*)smraw;

    const size_t base = ((size_t)b * NHD + h) * (NTOK * HDIM);
    const __half* qp = g_q + base;
    const __half* kp = g_k + base;
    const __half* vp = g_v + base;
    const float* bm = g_bm + ((size_t)(w * NHD + h)) * 64 * 68;

#pragma unroll
    for (int c = ht; c < 256; c += 128) {
        int r = c >> 2, off = (c & 3) * 8;
        cp16(&Qs[r][off], qp + r * 32 + off);
    }
#pragma unroll
    for (int c = ht; c < 256; c += 128) {
        int r = c >> 2, off = (c & 3) * 8;
        cp16(&Ks[r][off], kp + r * 32 + off);
    }
#pragma unroll
    for (int c = ht; c < 256; c += 128) {
        int r = c >> 2, off = (c & 3) * 8;
        cp16(&Vs[r][off], vp + r * 32 + off);
    }
    for (int c = tid; c < 1088; c += 256)
        cp16((char*)bmS + c * 16, (const char*)bm + c * 16);
    asm volatile("cp.async.commit_group;" ::: "memory");
    asm volatile("cp.async.wait_group 0;" ::: "memory");
    __syncthreads();

    float sc[7][4];
#pragma unroll
    for (int nt = 0; nt < 7; nt++)
#pragma unroll
        for (int e = 0; e < 4; e++) sc[nt][e] = 0.f;

#pragma unroll
    for (int ks = 0; ks < 2; ks++) {
        const int kc = ks * 16;
        uint32_t a[4];
        ldsm4(a, &Qs[m0 + (lane & 15)][kc + ((lane & 16) >> 1)]);
#pragma unroll
        for (int t = 0; t < 4; t++) {
            uint32_t bk_[4];
            ldsm4(bk_, &Ks[t * 16 + (lane & 7) + ((lane & 16) >> 1)][kc + (lane & 8)]);
            mma16816(sc[2 * t], a[0], a[1], a[2], a[3], bk_[0], bk_[1]);
            if (2 * t + 1 < 7)
                mma16816(sc[2 * t + 1], a[0], a[1], a[2], a[3], bk_[2], bk_[3]);
        }
    }

    const int i0 = m0 + g, i1 = i0 + 8;
#pragma unroll
    for (int nt = 0; nt < 7; nt++) {
        int jc = nt * 8 + 2 * tig;
        float2 v0 = *(const float2*)&bmS[i0 * 68 + jc];
        float2 v1 = *(const float2*)&bmS[i1 * 68 + jc];
        sc[nt][0] += v0.x; sc[nt][1] += v0.y;
        sc[nt][2] += v1.x; sc[nt][3] += v1.y;
    }

    float mx0 = -1e30f, mx1 = -1e30f;
#pragma unroll
    for (int nt = 0; nt < 7; nt++) {
        mx0 = fmaxf(mx0, fmaxf(sc[nt][0], sc[nt][1]));
        mx1 = fmaxf(mx1, fmaxf(sc[nt][2], sc[nt][3]));
    }
    mx0 = fmaxf(mx0, __shfl_xor_sync(0xffffffffu, mx0, 1));
    mx0 = fmaxf(mx0, __shfl_xor_sync(0xffffffffu, mx0, 2));
    mx1 = fmaxf(mx1, __shfl_xor_sync(0xffffffffu, mx1, 1));
    mx1 = fmaxf(mx1, __shfl_xor_sync(0xffffffffu, mx1, 2));

    float s0 = 0.f, s1 = 0.f;
#pragma unroll
    for (int nt = 0; nt < 7; nt++) {
        sc[nt][0] = __expf(sc[nt][0] - mx0); s0 += sc[nt][0];
        sc[nt][1] = __expf(sc[nt][1] - mx0); s0 += sc[nt][1];
        sc[nt][2] = __expf(sc[nt][2] - mx1); s1 += sc[nt][2];
        sc[nt][3] = __expf(sc[nt][3] - mx1); s1 += sc[nt][3];
    }
    s0 += __shfl_xor_sync(0xffffffffu, s0, 1);
    s0 += __shfl_xor_sync(0xffffffffu, s0, 2);
    s1 += __shfl_xor_sync(0xffffffffu, s1, 1);
    s1 += __shfl_xor_sync(0xffffffffu, s1, 2);
    const float r0 = 1.f / s0, r1 = 1.f / s1;

    uint32_t pa0[4], pa1[4], pa2[4], pa3[4];
#pragma unroll
    for (int kt = 0; kt < 4; kt++) {
        pa0[kt] = packh2(sc[2 * kt][0], sc[2 * kt][1]);
        pa1[kt] = packh2(sc[2 * kt][2], sc[2 * kt][3]);
        if (2 * kt + 1 < 7) {
            pa2[kt] = packh2(sc[2 * kt + 1][0], sc[2 * kt + 1][1]);
            pa3[kt] = packh2(sc[2 * kt + 1][2], sc[2 * kt + 1][3]);
        } else {
            pa2[kt] = 0u;
            pa3[kt] = 0u;
        }
    }

    float o[4][4];
#pragma unroll
    for (int nt = 0; nt < 4; nt++)
#pragma unroll
        for (int e = 0; e < 4; e++) o[nt][e] = 0.f;

#pragma unroll
    for (int kt = 0; kt < 4; kt++) {
        const int kc = kt * 16;
        uint32_t bv0[4], bv1[4];
        ldsm4t(bv0, &Vs[kc + (lane & 15)][0  + ((lane & 16) >> 1)]);
        ldsm4t(bv1, &Vs[kc + (lane & 15)][16 + ((lane & 16) >> 1)]);
        mma16816(o[0], pa0[kt], pa1[kt], pa2[kt], pa3[kt], bv0[0], bv0[1]);
        mma16816(o[1], pa0[kt], pa1[kt], pa2[kt], pa3[kt], bv0[2], bv0[3]);
        mma16816(o[2], pa0[kt], pa1[kt], pa2[kt], pa3[kt], bv1[0], bv1[1]);
        mma16816(o[3], pa0[kt], pa1[kt], pa2[kt], pa3[kt], bv1[2], bv1[3]);
    }

    __syncthreads();
    float* Osw = Os + warp * 512;
#pragma unroll
    for (int nt = 0; nt < 4; nt++) {
        int d = nt * 8 + 2 * tig;
        *(float2*)&Osw[g * 32 + d]       = make_float2(o[nt][0] * r0, o[nt][1] * r0);
        *(float2*)&Osw[(g + 8) * 32 + d] = make_float2(o[nt][2] * r1, o[nt][3] * r1);
    }
    __syncwarp();
#pragma unroll
    for (int it = lane; it < 128; it += 32) {
        int r = it >> 3, c = (it & 7) * 4;
        int row = m0 + r;
        if (row < NTOK)
            *(float4*)(out + ((size_t)b * NTOK + row) * DMODEL + h * HDIM + c) =
                *(const float4*)&Osw[r * 32 + c];
    }
}

extern "C" void kernel_launch(void* const* d_in, const int* in_sizes, int n_in,
                              void* d_out, int out_size)
{
    (void)in_sizes; (void)n_in; (void)out_size;
    const float* hidden = (const float*)d_in[0];
    const float* amask  = (const float*)d_in[1];
    const float* wq     = (const float*)d_in[2];
    const float* bq     = (const float*)d_in[3];
    const float* wk     = (const float*)d_in[4];
    const float* bk     = (const float*)d_in[5];
    const float* wv     = (const float*)d_in[6];
    const float* bv     = (const float*)d_in[7];
    const float* table  = (const float*)d_in[8];
    float* out = (float*)d_out;

    cudaFuncSetAttribute(qkv_kernel, cudaFuncAttributeMaxDynamicSharedMemorySize,
                         QKV_SMEM);

    prep<<<1280, 256>>>(amask, table, wq, wk, wv);
    qkv_kernel<<<dim3(6, 1568), 256, QKV_SMEM>>>(hidden, bq, bk, bv);
    attn_kernel<<<dim3(2048, NHD), 256>>>(out);
}

// round 12
// speedup vs baseline: 1.1444x; 1.1444x over previous
#include <cuda_runtime.h>
#include <cuda_fp16.h>
#include <cstdint>

#define NTOK   49
#define NHD    8
#define HDIM   32
#define DMODEL 256
#define NBATCH 4096
#define NWIN   64
#define MROWS  (NBATCH * NTOK)   // 200704

// fp16 scratch. +2048 halves padding: attn loads 64 padded rows per (b,h).
__device__ __half g_q[(size_t)NBATCH * NHD * NTOK * HDIM + 2048];
__device__ __half g_k[(size_t)NBATCH * NHD * NTOK * HDIM + 2048];
__device__ __half g_v[(size_t)NBATCH * NHD * NTOK * HDIM + 2048];
__device__ __half g_x[(size_t)MROWS * DMODEL];
__device__ __half g_w[3 * 256 * 256];           // [mat][n][k] (W transposed)
__device__ float  g_bm[NWIN * NHD * 64 * 68];   // combined mask+bias, 68-f rows

__device__ __forceinline__ void mma16816(float c[4],
                                         uint32_t a0, uint32_t a1, uint32_t a2, uint32_t a3,
                                         uint32_t b0, uint32_t b1) {
    asm volatile(
        "mma.sync.aligned.m16n8k16.row.col.f32.f16.f16.f32 "
        "{%0,%1,%2,%3}, {%4,%5,%6,%7}, {%8,%9}, {%0,%1,%2,%3};"
        : "+f"(c[0]), "+f"(c[1]), "+f"(c[2]), "+f"(c[3])
        : "r"(a0), "r"(a1), "r"(a2), "r"(a3), "r"(b0), "r"(b1));
}

__device__ __forceinline__ void ldsm4(uint32_t r[4], const void* p) {
    uint32_t a = (uint32_t)__cvta_generic_to_shared(p);
    asm volatile("ldmatrix.sync.aligned.m8n8.x4.shared.b16 {%0,%1,%2,%3}, [%4];"
                 : "=r"(r[0]), "=r"(r[1]), "=r"(r[2]), "=r"(r[3]) : "r"(a));
}

__device__ __forceinline__ void ldsm4t(uint32_t r[4], const void* p) {
    uint32_t a = (uint32_t)__cvta_generic_to_shared(p);
    asm volatile("ldmatrix.sync.aligned.m8n8.x4.trans.shared.b16 {%0,%1,%2,%3}, [%4];"
                 : "=r"(r[0]), "=r"(r[1]), "=r"(r[2]), "=r"(r[3]) : "r"(a));
}

__device__ __forceinline__ void cp16(void* s, const void* g) {
    uint32_t sa = (uint32_t)__cvta_generic_to_shared(s);
    asm volatile("cp.async.cg.shared.global [%0], [%1], 16;" :: "r"(sa), "l"(g));
}

__device__ __forceinline__ uint32_t packh2(float x, float y) {
    __half2 h = __floats2half2_rn(x, y);
    return *(uint32_t*)&h;
}

// ---------------------------------------------------------------------------
// prep_all: single launch for every precompute.
//   blocks [0, 50176)        : X fp32 -> fp16 (4 elems/thread, coalesced)
//   blocks [50176, 50688)    : combined bias+mask g_bm[w][h][64][68]
//   blocks [50688, 51456)    : W transpose+convert g_w[mat][n][k]
// ---------------------------------------------------------------------------
__global__ __launch_bounds__(256) void prep_all(
    const float* __restrict__ X,
    const float* __restrict__ mask, const float* __restrict__ table,
    const float* __restrict__ wq, const float* __restrict__ wk,
    const float* __restrict__ wv)
{
    const int id = blockIdx.x;
    if (id < 50176) {
        size_t t = (size_t)id * 256 + threadIdx.x;
        float4 v = ((const float4*)X)[t];
        __half2* o = (__half2*)(g_x + t * 4);
        o[0] = __floats2half2_rn(v.x, v.y);
        o[1] = __floats2half2_rn(v.z, v.w);
    } else if (id < 50688) {
        const int bid = id - 50176;
        const int w = bid >> 3, h = bid & 7;
        float* dst = g_bm + ((size_t)(w * NHD + h)) * 64 * 68;
        for (int idx = threadIdx.x; idx < 64 * 68; idx += 256) {
            int i = idx / 68, j = idx - i * 68;
            float v;
            if (j >= NTOK)      v = -1e30f;
            else if (i >= NTOK) v = 0.f;
            else {
                int ih = i / 7, iw = i - ih * 7;
                int jh = j / 7, jw = j - jh * 7;
                int r = (ih - jh + 6) * 13 + (iw - jw + 6);
                v = mask[((size_t)w * NTOK + i) * NTOK + j] + table[r * NHD + h];
            }
            dst[idx] = v;
        }
    } else {
        const int wid = id - 50688;
        const int mat = wid >> 8, k = wid & 255, n = threadIdx.x;
        const float* W = (mat == 0) ? wq : (mat == 1) ? wk : wv;
        g_w[((size_t)mat * 256 + n) * 256 + k] = __float2half_rn(W[k * 256 + n]);
    }
}

// ---------------------------------------------------------------------------
// Kernel A: QKV projection (exact round-9 config; measured 262us — the
// legacy-HMMA issue roofline; do not modify). BM=128, BN=128, BK=64,
// 2-stage cp.async. 72KB smem -> 2 CTAs/SM. 8 warps (2m x 4n), warp 64x32.
// ---------------------------------------------------------------------------
#define QKV_SMEM 73728

__global__ __launch_bounds__(256, 2) void qkv_kernel(
    const float* __restrict__ bq, const float* __restrict__ bk,
    const float* __restrict__ bv)
{
    extern __shared__ __half sm[];   // stage s: As at s*18432, Bs at +9216 (halves)

    const int bx = blockIdx.x, by = blockIdx.y;
    const int tid = threadIdx.x;
    const int warp = tid >> 5, lane = tid & 31;
    const int wm = warp & 1, wn = warp >> 1;
    const int g = lane >> 2, tig = lane & 3;

    const int mat   = bx >> 1;
    const int ncol0 = (bx & 1) * 128;
    const float* bias = (mat == 0) ? bq : (mat == 1) ? bk : bv;

    const __half* xrow  = g_x + (size_t)by * 128 * 256;
    const __half* wbase = g_w + ((size_t)mat * 256 + ncol0) * 256;

    auto loadStage = [&](int s, int kp) {
        __half* A = sm + s * 18432;
        __half* B = sm + s * 18432 + 9216;
        const __half* xs = xrow + kp * 64;
        const __half* ws = wbase + kp * 64;
#pragma unroll
        for (int c = tid; c < 1024; c += 256) {
            int r = c >> 3, off = (c & 7) * 8;
            cp16(A + r * 72 + off, xs + (size_t)r * 256 + off);
        }
#pragma unroll
        for (int c = tid; c < 1024; c += 256) {
            int r = c >> 3, off = (c & 7) * 8;
            cp16(B + r * 72 + off, ws + (size_t)r * 256 + off);
        }
        asm volatile("cp.async.commit_group;" ::: "memory");
    };

    loadStage(0, 0);
    loadStage(1, 1);

    float acc[4][4][4];
#pragma unroll
    for (int mt = 0; mt < 4; mt++)
#pragma unroll
        for (int nt = 0; nt < 4; nt++)
#pragma unroll
            for (int e = 0; e < 4; e++) acc[mt][nt][e] = 0.f;

    const int aRow = wm * 64 + (lane & 15);
    const int aCol = (lane & 16) >> 1;
    const int bRow = wn * 32 + (lane & 7) + ((lane & 16) >> 1);
    const int bCol = lane & 8;

#pragma unroll
    for (int kp = 0; kp < 4; kp++) {
        if (kp < 3) asm volatile("cp.async.wait_group 1;" ::: "memory");
        else        asm volatile("cp.async.wait_group 0;" ::: "memory");
        __syncthreads();

        const __half* A = sm + (kp & 1) * 18432;
        const __half* B = sm + (kp & 1) * 18432 + 9216;

#pragma unroll
        for (int ks = 0; ks < 4; ks++) {
            const int kc = ks * 16;
            uint32_t bf0[4], bf1[4];
            ldsm4(bf0, B + bRow * 72 + kc + bCol);
            ldsm4(bf1, B + (bRow + 16) * 72 + kc + bCol);
#pragma unroll
            for (int mt = 0; mt < 4; mt++) {
                uint32_t a[4];
                ldsm4(a, A + (aRow + mt * 16) * 72 + kc + aCol);
                mma16816(acc[mt][0], a[0], a[1], a[2], a[3], bf0[0], bf0[1]);
                mma16816(acc[mt][1], a[0], a[1], a[2], a[3], bf0[2], bf0[3]);
                mma16816(acc[mt][2], a[0], a[1], a[2], a[3], bf1[0], bf1[1]);
                mma16816(acc[mt][3], a[0], a[1], a[2], a[3], bf1[2], bf1[3]);
            }
        }

        if (kp < 2) {
            __syncthreads();
            loadStage(kp & 1, kp + 2);
        }
    }

    __half* outp = (mat == 0) ? g_q : (mat == 1) ? g_k : g_v;
    const float scale = (mat == 0) ? 0.17677669529663687f : 1.0f;
#pragma unroll
    for (int mt = 0; mt < 4; mt++) {
#pragma unroll
        for (int hf = 0; hf < 2; hf++) {
            int m = by * 128 + wm * 64 + mt * 16 + g + hf * 8;
            int b = m / NTOK, n = m - b * NTOK;
#pragma unroll
            for (int nt = 0; nt < 4; nt++) {
                int c = ncol0 + wn * 32 + nt * 8 + 2 * tig;
                int h = c >> 5, d = c & 31;
                float v0 = (acc[mt][nt][hf * 2 + 0] + bias[c]) * scale;
                float v1 = (acc[mt][nt][hf * 2 + 1] + bias[c + 1]) * scale;
                *(__half2*)(outp + ((((size_t)b * NHD + h) * NTOK + n) * HDIM + d)) =
                    __floats2half2_rn(v0, v1);
            }
        }
    }
}

// ---------------------------------------------------------------------------
// Kernel B: windowed attention (exact round-9 config — measured optimum).
// Two windows per CTA sharing one bm tile; P stays in registers.
// ---------------------------------------------------------------------------
#define WINBUF 15360   // Qs 5120 + Ks 5120 + Vs 5120

__global__ __launch_bounds__(256, 3) void attn_kernel(float* __restrict__ out)
{
    __shared__ alignas(128) char smraw[2 * WINBUF + 17408];

    const int b0 = blockIdx.x;          // 0..2047
    const int h  = blockIdx.y;
    const int w  = b0 & (NWIN - 1);

    const int tid = threadIdx.x;
    const int warp = tid >> 5, lane = tid & 31;
    const int half = warp >> 2;
    const int wl   = warp & 3;
    const int ht   = tid & 127;
    const int g = lane >> 2, tig = lane & 3;
    const int m0 = wl * 16;

    const int b = b0 + half * 2048;

    char* hb = smraw + half * WINBUF;
    __half (*Qs)[40] = (__half(*)[40])(hb);
    __half (*Ks)[40] = (__half(*)[40])(hb + 5120);
    __half (*Vs)[40] = (__half(*)[40])(hb + 10240);
    float* bmS = (float*)(smraw + 2 * WINBUF);
    float* Os  = (float*)smraw;

    const size_t base = ((size_t)b * NHD + h) * (NTOK * HDIM);
    const __half* qp = g_q + base;
    const __half* kp = g_k + base;
    const __half* vp = g_v + base;
    const float* bm = g_bm + ((size_t)(w * NHD + h)) * 64 * 68;

#pragma unroll
    for (int c = ht; c < 256; c += 128) {
        int r = c >> 2, off = (c & 3) * 8;
        cp16(&Qs[r][off], qp + r * 32 + off);
    }
#pragma unroll
    for (int c = ht; c < 256; c += 128) {
        int r = c >> 2, off = (c & 3) * 8;
        cp16(&Ks[r][off], kp + r * 32 + off);
    }
#pragma unroll
    for (int c = ht; c < 256; c += 128) {
        int r = c >> 2, off = (c & 3) * 8;
        cp16(&Vs[r][off], vp + r * 32 + off);
    }
    for (int c = tid; c < 1088; c += 256)
        cp16((char*)bmS + c * 16, (const char*)bm + c * 16);
    asm volatile("cp.async.commit_group;" ::: "memory");
    asm volatile("cp.async.wait_group 0;" ::: "memory");
    __syncthreads();

    float sc[7][4];
#pragma unroll
    for (int nt = 0; nt < 7; nt++)
#pragma unroll
        for (int e = 0; e < 4; e++) sc[nt][e] = 0.f;

#pragma unroll
    for (int ks = 0; ks < 2; ks++) {
        const int kc = ks * 16;
        uint32_t a[4];
        ldsm4(a, &Qs[m0 + (lane & 15)][kc + ((lane & 16) >> 1)]);
#pragma unroll
        for (int t = 0; t < 4; t++) {
            uint32_t bk_[4];
            ldsm4(bk_, &Ks[t * 16 + (lane & 7) + ((lane & 16) >> 1)][kc + (lane & 8)]);
            mma16816(sc[2 * t], a[0], a[1], a[2], a[3], bk_[0], bk_[1]);
            if (2 * t + 1 < 7)
                mma16816(sc[2 * t + 1], a[0], a[1], a[2], a[3], bk_[2], bk_[3]);
        }
    }

    const int i0 = m0 + g, i1 = i0 + 8;
#pragma unroll
    for (int nt = 0; nt < 7; nt++) {
        int jc = nt * 8 + 2 * tig;
        float2 v0 = *(const float2*)&bmS[i0 * 68 + jc];
        float2 v1 = *(const float2*)&bmS[i1 * 68 + jc];
        sc[nt][0] += v0.x; sc[nt][1] += v0.y;
        sc[nt][2] += v1.x; sc[nt][3] += v1.y;
    }

    float mx0 = -1e30f, mx1 = -1e30f;
#pragma unroll
    for (int nt = 0; nt < 7; nt++) {
        mx0 = fmaxf(mx0, fmaxf(sc[nt][0], sc[nt][1]));
        mx1 = fmaxf(mx1, fmaxf(sc[nt][2], sc[nt][3]));
    }
    mx0 = fmaxf(mx0, __shfl_xor_sync(0xffffffffu, mx0, 1));
    mx0 = fmaxf(mx0, __shfl_xor_sync(0xffffffffu, mx0, 2));
    mx1 = fmaxf(mx1, __shfl_xor_sync(0xffffffffu, mx1, 1));
    mx1 = fmaxf(mx1, __shfl_xor_sync(0xffffffffu, mx1, 2));

    float s0 = 0.f, s1 = 0.f;
#pragma unroll
    for (int nt = 0; nt < 7; nt++) {
        sc[nt][0] = __expf(sc[nt][0] - mx0); s0 += sc[nt][0];
        sc[nt][1] = __expf(sc[nt][1] - mx0); s0 += sc[nt][1];
        sc[nt][2] = __expf(sc[nt][2] - mx1); s1 += sc[nt][2];
        sc[nt][3] = __expf(sc[nt][3] - mx1); s1 += sc[nt][3];
    }
    s0 += __shfl_xor_sync(0xffffffffu, s0, 1);
    s0 += __shfl_xor_sync(0xffffffffu, s0, 2);
    s1 += __shfl_xor_sync(0xffffffffu, s1, 1);
    s1 += __shfl_xor_sync(0xffffffffu, s1, 2);
    const float r0 = 1.f / s0, r1 = 1.f / s1;

    uint32_t pa0[4], pa1[4], pa2[4], pa3[4];
#pragma unroll
    for (int kt = 0; kt < 4; kt++) {
        pa0[kt] = packh2(sc[2 * kt][0], sc[2 * kt][1]);
        pa1[kt] = packh2(sc[2 * kt][2], sc[2 * kt][3]);
        if (2 * kt + 1 < 7) {
            pa2[kt] = packh2(sc[2 * kt + 1][0], sc[2 * kt + 1][1]);
            pa3[kt] = packh2(sc[2 * kt + 1][2], sc[2 * kt + 1][3]);
        } else {
            pa2[kt] = 0u;
            pa3[kt] = 0u;
        }
    }

    float o[4][4];
#pragma unroll
    for (int nt = 0; nt < 4; nt++)
#pragma unroll
        for (int e = 0; e < 4; e++) o[nt][e] = 0.f;

#pragma unroll
    for (int kt = 0; kt < 4; kt++) {
        const int kc = kt * 16;
        uint32_t bv0[4], bv1[4];
        ldsm4t(bv0, &Vs[kc + (lane & 15)][0  + ((lane & 16) >> 1)]);
        ldsm4t(bv1, &Vs[kc + (lane & 15)][16 + ((lane & 16) >> 1)]);
        mma16816(o[0], pa0[kt], pa1[kt], pa2[kt], pa3[kt], bv0[0], bv0[1]);
        mma16816(o[1], pa0[kt], pa1[kt], pa2[kt], pa3[kt], bv0[2], bv0[3]);
        mma16816(o[2], pa0[kt], pa1[kt], pa2[kt], pa3[kt], bv1[0], bv1[1]);
        mma16816(o[3], pa0[kt], pa1[kt], pa2[kt], pa3[kt], bv1[2], bv1[3]);
    }

    __syncthreads();
    float* Osw = Os + warp * 512;
#pragma unroll
    for (int nt = 0; nt < 4; nt++) {
        int d = nt * 8 + 2 * tig;
        *(float2*)&Osw[g * 32 + d]       = make_float2(o[nt][0] * r0, o[nt][1] * r0);
        *(float2*)&Osw[(g + 8) * 32 + d] = make_float2(o[nt][2] * r1, o[nt][3] * r1);
    }
    __syncwarp();
#pragma unroll
    for (int it = lane; it < 128; it += 32) {
        int r = it >> 3, c = (it & 7) * 4;
        int row = m0 + r;
        if (row < NTOK)
            *(float4*)(out + ((size_t)b * NTOK + row) * DMODEL + h * HDIM + c) =
                *(const float4*)&Osw[r * 32 + c];
    }
}

extern "C" void kernel_launch(void* const* d_in, const int* in_sizes, int n_in,
                              void* d_out, int out_size)
{
    (void)in_sizes; (void)n_in; (void)out_size;
    const float* hidden = (const float*)d_in[0];
    const float* amask  = (const float*)d_in[1];
    const float* wq     = (const float*)d_in[2];
    const float* bq     = (const float*)d_in[3];
    const float* wk     = (const float*)d_in[4];
    const float* bk     = (const float*)d_in[5];
    const float* wv     = (const float*)d_in[6];
    const float* bv     = (const float*)d_in[7];
    const float* table  = (const float*)d_in[8];
    float* out = (float*)d_out;

    cudaFuncSetAttribute(qkv_kernel, cudaFuncAttributeMaxDynamicSharedMemorySize,
                         QKV_SMEM);

    prep_all<<<51456, 256>>>(hidden, amask, table, wq, wk, wv);
    qkv_kernel<<<dim3(6, 1568), 256, QKV_SMEM>>>(bq, bk, bv);
    attn_kernel<<<dim3(2048, NHD), 256>>>(out);
}

// round 13
// speedup vs baseline: 1.1457x; 1.0011x over previous
#include <cuda_runtime.h>
#include <cuda_fp16.h>
#include <cstdint>

#define NTOK   49
#define NHD    8
#define HDIM   32
#define DMODEL 256
#define NBATCH 4096
#define NWIN   64
#define MROWS  (NBATCH * NTOK)   // 200704

// fp16 scratch. +2048 halves padding: attn loads 64 padded rows per (b,h).
__device__ __half g_q[(size_t)NBATCH * NHD * NTOK * HDIM + 2048];
__device__ __half g_k[(size_t)NBATCH * NHD * NTOK * HDIM + 2048];
__device__ __half g_v[(size_t)NBATCH * NHD * NTOK * HDIM + 2048];
__device__ __half g_x[(size_t)MROWS * DMODEL];
__device__ __half g_w[3 * 256 * 256];           // [mat][n][k] (W transposed)
__device__ float  g_bm[NWIN * NHD * 64 * 68];   // combined mask+bias, 68-f rows

__device__ __forceinline__ void mma16816(float c[4],
                                         uint32_t a0, uint32_t a1, uint32_t a2, uint32_t a3,
                                         uint32_t b0, uint32_t b1) {
    asm volatile(
        "mma.sync.aligned.m16n8k16.row.col.f32.f16.f16.f32 "
        "{%0,%1,%2,%3}, {%4,%5,%6,%7}, {%8,%9}, {%0,%1,%2,%3};"
        : "+f"(c[0]), "+f"(c[1]), "+f"(c[2]), "+f"(c[3])
        : "r"(a0), "r"(a1), "r"(a2), "r"(a3), "r"(b0), "r"(b1));
}

__device__ __forceinline__ void ldsm4(uint32_t r[4], const void* p) {
    uint32_t a = (uint32_t)__cvta_generic_to_shared(p);
    asm volatile("ldmatrix.sync.aligned.m8n8.x4.shared.b16 {%0,%1,%2,%3}, [%4];"
                 : "=r"(r[0]), "=r"(r[1]), "=r"(r[2]), "=r"(r[3]) : "r"(a));
}

__device__ __forceinline__ void ldsm4t(uint32_t r[4], const void* p) {
    uint32_t a = (uint32_t)__cvta_generic_to_shared(p);
    asm volatile("ldmatrix.sync.aligned.m8n8.x4.trans.shared.b16 {%0,%1,%2,%3}, [%4];"
                 : "=r"(r[0]), "=r"(r[1]), "=r"(r[2]), "=r"(r[3]) : "r"(a));
}

__device__ __forceinline__ void cp16(void* s, const void* g) {
    uint32_t sa = (uint32_t)__cvta_generic_to_shared(s);
    asm volatile("cp.async.cg.shared.global [%0], [%1], 16;" :: "r"(sa), "l"(g));
}

__device__ __forceinline__ uint32_t packh2(float x, float y) {
    __half2 h = __floats2half2_rn(x, y);
    return *(uint32_t*)&h;
}

// ---------------------------------------------------------------------------
// prep_all: single launch for every precompute (measured 58.6us, DRAM-bound).
//   blocks [0, 50176)     : X fp32 -> fp16
//   blocks [50176, 50688) : combined bias+mask g_bm[w][h][64][68]
//   blocks [50688, 51456) : W transpose+convert g_w[mat][n][k]
// ---------------------------------------------------------------------------
__global__ __launch_bounds__(256) void prep_all(
    const float* __restrict__ X,
    const float* __restrict__ mask, const float* __restrict__ table,
    const float* __restrict__ wq, const float* __restrict__ wk,
    const float* __restrict__ wv)
{
    const int id = blockIdx.x;
    if (id < 50176) {
        size_t t = (size_t)id * 256 + threadIdx.x;
        float4 v = ((const float4*)X)[t];
        __half2* o = (__half2*)(g_x + t * 4);
        o[0] = __floats2half2_rn(v.x, v.y);
        o[1] = __floats2half2_rn(v.z, v.w);
    } else if (id < 50688) {
        const int bid = id - 50176;
        const int w = bid >> 3, h = bid & 7;
        float* dst = g_bm + ((size_t)(w * NHD + h)) * 64 * 68;
        for (int idx = threadIdx.x; idx < 64 * 68; idx += 256) {
            int i = idx / 68, j = idx - i * 68;
            float v;
            if (j >= NTOK)      v = -1e30f;
            else if (i >= NTOK) v = 0.f;
            else {
                int ih = i / 7, iw = i - ih * 7;
                int jh = j / 7, jw = j - jh * 7;
                int r = (ih - jh + 6) * 13 + (iw - jw + 6);
                v = mask[((size_t)w * NTOK + i) * NTOK + j] + table[r * NHD + h];
            }
            dst[idx] = v;
        }
    } else {
        const int wid = id - 50688;
        const int mat = wid >> 8, k = wid & 255, n = threadIdx.x;
        const float* W = (mat == 0) ? wq : (mat == 1) ? wk : wv;
        g_w[((size_t)mat * 256 + n) * 256 + k] = __float2half_rn(W[k * 256 + n]);
    }
}

// ---------------------------------------------------------------------------
// Kernel A: QKV projection (exact round-9 config; measured 262us — the
// legacy-HMMA issue roofline; do not modify).
// ---------------------------------------------------------------------------
#define QKV_SMEM 73728

__global__ __launch_bounds__(256, 2) void qkv_kernel(
    const float* __restrict__ bq, const float* __restrict__ bk,
    const float* __restrict__ bv)
{
    extern __shared__ __half sm[];   // stage s: As at s*18432, Bs at +9216 (halves)

    const int bx = blockIdx.x, by = blockIdx.y;
    const int tid = threadIdx.x;
    const int warp = tid >> 5, lane = tid & 31;
    const int wm = warp & 1, wn = warp >> 1;
    const int g = lane >> 2, tig = lane & 3;

    const int mat   = bx >> 1;
    const int ncol0 = (bx & 1) * 128;
    const float* bias = (mat == 0) ? bq : (mat == 1) ? bk : bv;

    const __half* xrow  = g_x + (size_t)by * 128 * 256;
    const __half* wbase = g_w + ((size_t)mat * 256 + ncol0) * 256;

    auto loadStage = [&](int s, int kp) {
        __half* A = sm + s * 18432;
        __half* B = sm + s * 18432 + 9216;
        const __half* xs = xrow + kp * 64;
        const __half* ws = wbase + kp * 64;
#pragma unroll
        for (int c = tid; c < 1024; c += 256) {
            int r = c >> 3, off = (c & 7) * 8;
            cp16(A + r * 72 + off, xs + (size_t)r * 256 + off);
        }
#pragma unroll
        for (int c = tid; c < 1024; c += 256) {
            int r = c >> 3, off = (c & 7) * 8;
            cp16(B + r * 72 + off, ws + (size_t)r * 256 + off);
        }
        asm volatile("cp.async.commit_group;" ::: "memory");
    };

    loadStage(0, 0);
    loadStage(1, 1);

    float acc[4][4][4];
#pragma unroll
    for (int mt = 0; mt < 4; mt++)
#pragma unroll
        for (int nt = 0; nt < 4; nt++)
#pragma unroll
            for (int e = 0; e < 4; e++) acc[mt][nt][e] = 0.f;

    const int aRow = wm * 64 + (lane & 15);
    const int aCol = (lane & 16) >> 1;
    const int bRow = wn * 32 + (lane & 7) + ((lane & 16) >> 1);
    const int bCol = lane & 8;

#pragma unroll
    for (int kp = 0; kp < 4; kp++) {
        if (kp < 3) asm volatile("cp.async.wait_group 1;" ::: "memory");
        else        asm volatile("cp.async.wait_group 0;" ::: "memory");
        __syncthreads();

        const __half* A = sm + (kp & 1) * 18432;
        const __half* B = sm + (kp & 1) * 18432 + 9216;

#pragma unroll
        for (int ks = 0; ks < 4; ks++) {
            const int kc = ks * 16;
            uint32_t bf0[4], bf1[4];
            ldsm4(bf0, B + bRow * 72 + kc + bCol);
            ldsm4(bf1, B + (bRow + 16) * 72 + kc + bCol);
#pragma unroll
            for (int mt = 0; mt < 4; mt++) {
                uint32_t a[4];
                ldsm4(a, A + (aRow + mt * 16) * 72 + kc + aCol);
                mma16816(acc[mt][0], a[0], a[1], a[2], a[3], bf0[0], bf0[1]);
                mma16816(acc[mt][1], a[0], a[1], a[2], a[3], bf0[2], bf0[3]);
                mma16816(acc[mt][2], a[0], a[1], a[2], a[3], bf1[0], bf1[1]);
                mma16816(acc[mt][3], a[0], a[1], a[2], a[3], bf1[2], bf1[3]);
            }
        }

        if (kp < 2) {
            __syncthreads();
            loadStage(kp & 1, kp + 2);
        }
    }

    __half* outp = (mat == 0) ? g_q : (mat == 1) ? g_k : g_v;
    const float scale = (mat == 0) ? 0.17677669529663687f : 1.0f;
#pragma unroll
    for (int mt = 0; mt < 4; mt++) {
#pragma unroll
        for (int hf = 0; hf < 2; hf++) {
            int m = by * 128 + wm * 64 + mt * 16 + g + hf * 8;
            int b = m / NTOK, n = m - b * NTOK;
#pragma unroll
            for (int nt = 0; nt < 4; nt++) {
                int c = ncol0 + wn * 32 + nt * 8 + 2 * tig;
                int h = c >> 5, d = c & 31;
                float v0 = (acc[mt][nt][hf * 2 + 0] + bias[c]) * scale;
                float v1 = (acc[mt][nt][hf * 2 + 1] + bias[c + 1]) * scale;
                *(__half2*)(outp + ((((size_t)b * NHD + h) * NTOK + n) * HDIM + d)) =
                    __floats2half2_rn(v0, v1);
            }
        }
    }
}

// ---------------------------------------------------------------------------
// Kernel B: windowed attention, EIGHT windows per CTA sharing one bm tile.
// grid (512, 8). Windows b0 + 512*m (m=0..7) all have w = b0 & 63. 256 thr:
// half = warp>>2 processes window m = 2*it + half for it = 0..3, with
// double-buffered QKV stages (prefetch it+1 during compute of it).
// Per-window compute = round-9 pipeline (P in registers, 7 n-tiles).
// smem: 2 stages x 2 windows x 15360 + bm 17408 + Os 16384 = 95232
//   -> 2 CTAs/SM. bm traffic drops 279MB -> 70MB.
// ---------------------------------------------------------------------------
#define WINBUF    15360    // Qs 5120 + Ks 5120 + Vs 5120
#define ATTN_SMEM 95232

__global__ __launch_bounds__(256, 2) void attn_kernel(float* __restrict__ out)
{
    extern __shared__ char smraw[];

    const int b0 = blockIdx.x;          // 0..511
    const int h  = blockIdx.y;
    const int w  = b0 & (NWIN - 1);

    const int tid = threadIdx.x;
    const int warp = tid >> 5, lane = tid & 31;
    const int half = warp >> 2;
    const int wl   = warp & 3;
    const int ht   = tid & 127;
    const int g = lane >> 2, tig = lane & 3;
    const int m0 = wl * 16;

    float* bmS = (float*)(smraw + 61440);   // 64 x 68 floats, shared all iters
    float* Os  = (float*)(smraw + 78848);   // 8 warps x 512 floats

    const float* bm = g_bm + ((size_t)(w * NHD + h)) * 64 * 68;

    // Load this half's window for iteration it into stage s.
    auto loadWin = [&](int s, int it) {
        const int b = b0 + 512 * (2 * it + half);
        const size_t base = ((size_t)b * NHD + h) * (NTOK * HDIM);
        char* hb = smraw + s * 30720 + half * WINBUF;
        __half (*Qs)[40] = (__half(*)[40])(hb);
        __half (*Ks)[40] = (__half(*)[40])(hb + 5120);
        __half (*Vs)[40] = (__half(*)[40])(hb + 10240);
        const __half* qp = g_q + base;
        const __half* kp = g_k + base;
        const __half* vp = g_v + base;
#pragma unroll
        for (int c = ht; c < 256; c += 128) {
            int r = c >> 2, off = (c & 3) * 8;
            cp16(&Qs[r][off], qp + r * 32 + off);
        }
#pragma unroll
        for (int c = ht; c < 256; c += 128) {
            int r = c >> 2, off = (c & 3) * 8;
            cp16(&Ks[r][off], kp + r * 32 + off);
        }
#pragma unroll
        for (int c = ht; c < 256; c += 128) {
            int r = c >> 2, off = (c & 3) * 8;
            cp16(&Vs[r][off], vp + r * 32 + off);
        }
    };

    // Prologue: bm + stage0 (it=0) in group 0; stage1 (it=1) in group 1.
    for (int c = tid; c < 1088; c += 256)
        cp16((char*)bmS + c * 16, (const char*)bm + c * 16);
    loadWin(0, 0);
    asm volatile("cp.async.commit_group;" ::: "memory");
    loadWin(1, 1);
    asm volatile("cp.async.commit_group;" ::: "memory");

#pragma unroll
    for (int it = 0; it < 4; it++) {
        if (it < 3) asm volatile("cp.async.wait_group 1;" ::: "memory");
        else        asm volatile("cp.async.wait_group 0;" ::: "memory");
        __syncthreads();

        const int s = it & 1;
        char* hb = smraw + s * 30720 + half * WINBUF;
        __half (*Qs)[40] = (__half(*)[40])(hb);
        __half (*Ks)[40] = (__half(*)[40])(hb + 5120);
        __half (*Vs)[40] = (__half(*)[40])(hb + 10240);

        // --- scores = Q @ K^T (64 rows x 56 key cols: 7 n-tiles) ---
        float sc[7][4];
#pragma unroll
        for (int nt = 0; nt < 7; nt++)
#pragma unroll
            for (int e = 0; e < 4; e++) sc[nt][e] = 0.f;

#pragma unroll
        for (int ks = 0; ks < 2; ks++) {
            const int kc = ks * 16;
            uint32_t a[4];
            ldsm4(a, &Qs[m0 + (lane & 15)][kc + ((lane & 16) >> 1)]);
#pragma unroll
            for (int t = 0; t < 4; t++) {
                uint32_t bk_[4];
                ldsm4(bk_, &Ks[t * 16 + (lane & 7) + ((lane & 16) >> 1)][kc + (lane & 8)]);
                mma16816(sc[2 * t], a[0], a[1], a[2], a[3], bk_[0], bk_[1]);
                if (2 * t + 1 < 7)
                    mma16816(sc[2 * t + 1], a[0], a[1], a[2], a[3], bk_[2], bk_[3]);
            }
        }

        const int i0 = m0 + g, i1 = i0 + 8;
#pragma unroll
        for (int nt = 0; nt < 7; nt++) {
            int jc = nt * 8 + 2 * tig;
            float2 v0 = *(const float2*)&bmS[i0 * 68 + jc];
            float2 v1 = *(const float2*)&bmS[i1 * 68 + jc];
            sc[nt][0] += v0.x; sc[nt][1] += v0.y;
            sc[nt][2] += v1.x; sc[nt][3] += v1.y;
        }

        // --- softmax ---
        float mx0 = -1e30f, mx1 = -1e30f;
#pragma unroll
        for (int nt = 0; nt < 7; nt++) {
            mx0 = fmaxf(mx0, fmaxf(sc[nt][0], sc[nt][1]));
            mx1 = fmaxf(mx1, fmaxf(sc[nt][2], sc[nt][3]));
        }
        mx0 = fmaxf(mx0, __shfl_xor_sync(0xffffffffu, mx0, 1));
        mx0 = fmaxf(mx0, __shfl_xor_sync(0xffffffffu, mx0, 2));
        mx1 = fmaxf(mx1, __shfl_xor_sync(0xffffffffu, mx1, 1));
        mx1 = fmaxf(mx1, __shfl_xor_sync(0xffffffffu, mx1, 2));

        float s0 = 0.f, s1 = 0.f;
#pragma unroll
        for (int nt = 0; nt < 7; nt++) {
            sc[nt][0] = __expf(sc[nt][0] - mx0); s0 += sc[nt][0];
            sc[nt][1] = __expf(sc[nt][1] - mx0); s0 += sc[nt][1];
            sc[nt][2] = __expf(sc[nt][2] - mx1); s1 += sc[nt][2];
            sc[nt][3] = __expf(sc[nt][3] - mx1); s1 += sc[nt][3];
        }
        s0 += __shfl_xor_sync(0xffffffffu, s0, 1);
        s0 += __shfl_xor_sync(0xffffffffu, s0, 2);
        s1 += __shfl_xor_sync(0xffffffffu, s1, 1);
        s1 += __shfl_xor_sync(0xffffffffu, s1, 2);
        const float r0 = 1.f / s0, r1 = 1.f / s1;

        // --- pack P fragments in registers ---
        uint32_t pa0[4], pa1[4], pa2[4], pa3[4];
#pragma unroll
        for (int kt = 0; kt < 4; kt++) {
            pa0[kt] = packh2(sc[2 * kt][0], sc[2 * kt][1]);
            pa1[kt] = packh2(sc[2 * kt][2], sc[2 * kt][3]);
            if (2 * kt + 1 < 7) {
                pa2[kt] = packh2(sc[2 * kt + 1][0], sc[2 * kt + 1][1]);
                pa3[kt] = packh2(sc[2 * kt + 1][2], sc[2 * kt + 1][3]);
            } else {
                pa2[kt] = 0u;
                pa3[kt] = 0u;
            }
        }

        // --- ctx = P @ V ---
        float o[4][4];
#pragma unroll
        for (int nt = 0; nt < 4; nt++)
#pragma unroll
            for (int e = 0; e < 4; e++) o[nt][e] = 0.f;

#pragma unroll
        for (int kt = 0; kt < 4; kt++) {
            const int kc = kt * 16;
            uint32_t bv0[4], bv1[4];
            ldsm4t(bv0, &Vs[kc + (lane & 15)][0  + ((lane & 16) >> 1)]);
            ldsm4t(bv1, &Vs[kc + (lane & 15)][16 + ((lane & 16) >> 1)]);
            mma16816(o[0], pa0[kt], pa1[kt], pa2[kt], pa3[kt], bv0[0], bv0[1]);
            mma16816(o[1], pa0[kt], pa1[kt], pa2[kt], pa3[kt], bv0[2], bv0[3]);
            mma16816(o[2], pa0[kt], pa1[kt], pa2[kt], pa3[kt], bv1[0], bv1[1]);
            mma16816(o[3], pa0[kt], pa1[kt], pa2[kt], pa3[kt], bv1[2], bv1[3]);
        }

        // All reads of stage s complete; refill with window it+2.
        __syncthreads();
        if (it < 2) {
            loadWin(s, it + 2);
            asm volatile("cp.async.commit_group;" ::: "memory");
        }

        // --- stage output in this warp's private Os slice, write coalesced ---
        const int b = b0 + 512 * (2 * it + half);
        float* Osw = Os + warp * 512;   // [16][32]
#pragma unroll
        for (int nt = 0; nt < 4; nt++) {
            int d = nt * 8 + 2 * tig;
            *(float2*)&Osw[g * 32 + d]       = make_float2(o[nt][0] * r0, o[nt][1] * r0);
            *(float2*)&Osw[(g + 8) * 32 + d] = make_float2(o[nt][2] * r1, o[nt][3] * r1);
        }
        __syncwarp();
#pragma unroll
        for (int itx = lane; itx < 128; itx += 32) {
            int r = itx >> 3, c = (itx & 7) * 4;
            int row = m0 + r;
            if (row < NTOK)
                *(float4*)(out + ((size_t)b * NTOK + row) * DMODEL + h * HDIM + c) =
                    *(const float4*)&Osw[r * 32 + c];
        }
    }
}

extern "C" void kernel_launch(void* const* d_in, const int* in_sizes, int n_in,
                              void* d_out, int out_size)
{
    (void)in_sizes; (void)n_in; (void)out_size;
    const float* hidden = (const float*)d_in[0];
    const float* amask  = (const float*)d_in[1];
    const float* wq     = (const float*)d_in[2];
    const float* bq     = (const float*)d_in[3];
    const float* wk     = (const float*)d_in[4];
    const float* bk     = (const float*)d_in[5];
    const float* wv     = (const float*)d_in[6];
    const float* bv     = (const float*)d_in[7];
    const float* table  = (const float*)d_in[8];
    float* out = (float*)d_out;

    cudaFuncSetAttribute(qkv_kernel, cudaFuncAttributeMaxDynamicSharedMemorySize,
                         QKV_SMEM);
    cudaFuncSetAttribute(attn_kernel, cudaFuncAttributeMaxDynamicSharedMemorySize,
                         ATTN_SMEM);

    prep_all<<<51456, 256>>>(hidden, amask, table, wq, wk, wv);
    qkv_kernel<<<dim3(6, 1568), 256, QKV_SMEM>>>(bq, bk, bv);
    attn_kernel<<<dim3(512, NHD), 256, ATTN_SMEM>>>(out);
}

// round 14
// speedup vs baseline: 1.1967x; 1.0445x over previous
#include <cuda_runtime.h>
#include <cuda_fp16.h>
#include <cstdint>

#define NTOK   49
#define NHD    8
#define HDIM   32
#define DMODEL 256
#define NBATCH 4096
#define NWIN   64
#define MROWS  (NBATCH * NTOK)   // 200704
#define LOG2E  1.4426950408889634f

// fp16 scratch. +2048 halves padding: attn loads 64 padded rows per (b,h).
__device__ __half g_q[(size_t)NBATCH * NHD * NTOK * HDIM + 2048];
__device__ __half g_k[(size_t)NBATCH * NHD * NTOK * HDIM + 2048];
__device__ __half g_v[(size_t)NBATCH * NHD * NTOK * HDIM + 2048];
__device__ __half g_x[(size_t)MROWS * DMODEL];
__device__ __half g_w[3 * 256 * 256];           // [mat][n][k] (W transposed)
__device__ float  g_bm[NWIN * NHD * 64 * 68];   // (mask+bias)*log2e, padded

__device__ __forceinline__ void mma16816(float c[4],
                                         uint32_t a0, uint32_t a1, uint32_t a2, uint32_t a3,
                                         uint32_t b0, uint32_t b1) {
    asm volatile(
        "mma.sync.aligned.m16n8k16.row.col.f32.f16.f16.f32 "
        "{%0,%1,%2,%3}, {%4,%5,%6,%7}, {%8,%9}, {%0,%1,%2,%3};"
        : "+f"(c[0]), "+f"(c[1]), "+f"(c[2]), "+f"(c[3])
        : "r"(a0), "r"(a1), "r"(a2), "r"(a3), "r"(b0), "r"(b1));
}

__device__ __forceinline__ void ldsm4(uint32_t r[4], const void* p) {
    uint32_t a = (uint32_t)__cvta_generic_to_shared(p);
    asm volatile("ldmatrix.sync.aligned.m8n8.x4.shared.b16 {%0,%1,%2,%3}, [%4];"
                 : "=r"(r[0]), "=r"(r[1]), "=r"(r[2]), "=r"(r[3]) : "r"(a));
}

__device__ __forceinline__ void ldsm4t(uint32_t r[4], const void* p) {
    uint32_t a = (uint32_t)__cvta_generic_to_shared(p);
    asm volatile("ldmatrix.sync.aligned.m8n8.x4.trans.shared.b16 {%0,%1,%2,%3}, [%4];"
                 : "=r"(r[0]), "=r"(r[1]), "=r"(r[2]), "=r"(r[3]) : "r"(a));
}

__device__ __forceinline__ void cp16(void* s, const void* g) {
    uint32_t sa = (uint32_t)__cvta_generic_to_shared(s);
    asm volatile("cp.async.cg.shared.global [%0], [%1], 16;" :: "r"(sa), "l"(g));
}

__device__ __forceinline__ uint32_t packh2(float x, float y) {
    __half2 h = __floats2half2_rn(x, y);
    return *(uint32_t*)&h;
}

// ---------------------------------------------------------------------------
// prep_all: single launch for every precompute (DRAM-bound, ~58us).
//   blocks [0, 50176)     : X fp32 -> fp16
//   blocks [50176, 50688) : combined (mask+bias)*LOG2E  g_bm[w][h][64][68]
//   blocks [50688, 51456) : W transpose+convert g_w[mat][n][k]
// ---------------------------------------------------------------------------
__global__ __launch_bounds__(256) void prep_all(
    const float* __restrict__ X,
    const float* __restrict__ mask, const float* __restrict__ table,
    const float* __restrict__ wq, const float* __restrict__ wk,
    const float* __restrict__ wv)
{
    const int id = blockIdx.x;
    if (id < 50176) {
        size_t t = (size_t)id * 256 + threadIdx.x;
        float4 v = ((const float4*)X)[t];
        __half2* o = (__half2*)(g_x + t * 4);
        o[0] = __floats2half2_rn(v.x, v.y);
        o[1] = __floats2half2_rn(v.z, v.w);
    } else if (id < 50688) {
        const int bid = id - 50176;
        const int w = bid >> 3, h = bid & 7;
        float* dst = g_bm + ((size_t)(w * NHD + h)) * 64 * 68;
        for (int idx = threadIdx.x; idx < 64 * 68; idx += 256) {
            int i = idx / 68, j = idx - i * 68;
            float v;
            if (j >= NTOK)      v = -1e30f;
            else if (i >= NTOK) v = 0.f;
            else {
                int ih = i / 7, iw = i - ih * 7;
                int jh = j / 7, jw = j - jh * 7;
                int r = (ih - jh + 6) * 13 + (iw - jw + 6);
                v = (mask[((size_t)w * NTOK + i) * NTOK + j] + table[r * NHD + h])
                    * LOG2E;
            }
            dst[idx] = v;
        }
    } else {
        const int wid = id - 50688;
        const int mat = wid >> 8, k = wid & 255, n = threadIdx.x;
        const float* W = (mat == 0) ? wq : (mat == 1) ? wk : wv;
        g_w[((size_t)mat * 256 + n) * 256 + k] = __float2half_rn(W[k * 256 + n]);
    }
}

// ---------------------------------------------------------------------------
// Kernel A: QKV projection (round-9 config; measured 262us — the legacy-HMMA
// issue roofline; mainloop frozen). Only change: Q scale folds in LOG2E so
// attention softmax can use exp2 directly.
// ---------------------------------------------------------------------------
#define QKV_SMEM 73728

__global__ __launch_bounds__(256, 2) void qkv_kernel(
    const float* __restrict__ bq, const float* __restrict__ bk,
    const float* __restrict__ bv)
{
    extern __shared__ __half sm[];   // stage s: As at s*18432, Bs at +9216 (halves)

    const int bx = blockIdx.x, by = blockIdx.y;
    const int tid = threadIdx.x;
    const int warp = tid >> 5, lane = tid & 31;
    const int wm = warp & 1, wn = warp >> 1;
    const int g = lane >> 2, tig = lane & 3;

    const int mat   = bx >> 1;
    const int ncol0 = (bx & 1) * 128;
    const float* bias = (mat == 0) ? bq : (mat == 1) ? bk : bv;

    const __half* xrow  = g_x + (size_t)by * 128 * 256;
    const __half* wbase = g_w + ((size_t)mat * 256 + ncol0) * 256;

    auto loadStage = [&](int s, int kp) {
        __half* A = sm + s * 18432;
        __half* B = sm + s * 18432 + 9216;
        const __half* xs = xrow + kp * 64;
        const __half* ws = wbase + kp * 64;
#pragma unroll
        for (int c = tid; c < 1024; c += 256) {
            int r = c >> 3, off = (c & 7) * 8;
            cp16(A + r * 72 + off, xs + (size_t)r * 256 + off);
        }
#pragma unroll
        for (int c = tid; c < 1024; c += 256) {
            int r = c >> 3, off = (c & 7) * 8;
            cp16(B + r * 72 + off, ws + (size_t)r * 256 + off);
        }
        asm volatile("cp.async.commit_group;" ::: "memory");
    };

    loadStage(0, 0);
    loadStage(1, 1);

    float acc[4][4][4];
#pragma unroll
    for (int mt = 0; mt < 4; mt++)
#pragma unroll
        for (int nt = 0; nt < 4; nt++)
#pragma unroll
            for (int e = 0; e < 4; e++) acc[mt][nt][e] = 0.f;

    const int aRow = wm * 64 + (lane & 15);
    const int aCol = (lane & 16) >> 1;
    const int bRow = wn * 32 + (lane & 7) + ((lane & 16) >> 1);
    const int bCol = lane & 8;

#pragma unroll
    for (int kp = 0; kp < 4; kp++) {
        if (kp < 3) asm volatile("cp.async.wait_group 1;" ::: "memory");
        else        asm volatile("cp.async.wait_group 0;" ::: "memory");
        __syncthreads();

        const __half* A = sm + (kp & 1) * 18432;
        const __half* B = sm + (kp & 1) * 18432 + 9216;

#pragma unroll
        for (int ks = 0; ks < 4; ks++) {
            const int kc = ks * 16;
            uint32_t bf0[4], bf1[4];
            ldsm4(bf0, B + bRow * 72 + kc + bCol);
            ldsm4(bf1, B + (bRow + 16) * 72 + kc + bCol);
#pragma unroll
            for (int mt = 0; mt < 4; mt++) {
                uint32_t a[4];
                ldsm4(a, A + (aRow + mt * 16) * 72 + kc + aCol);
                mma16816(acc[mt][0], a[0], a[1], a[2], a[3], bf0[0], bf0[1]);
                mma16816(acc[mt][1], a[0], a[1], a[2], a[3], bf0[2], bf0[3]);
                mma16816(acc[mt][2], a[0], a[1], a[2], a[3], bf1[0], bf1[1]);
                mma16816(acc[mt][3], a[0], a[1], a[2], a[3], bf1[2], bf1[3]);
            }
        }

        if (kp < 2) {
            __syncthreads();
            loadStage(kp & 1, kp + 2);
        }
    }

    __half* outp = (mat == 0) ? g_q : (mat == 1) ? g_k : g_v;
    // Q scale: 1/sqrt(32) * log2(e)  (softmax runs in exp2 domain)
    const float scale = (mat == 0) ? 0.17677669529663687f * LOG2E : 1.0f;
#pragma unroll
    for (int mt = 0; mt < 4; mt++) {
#pragma unroll
        for (int hf = 0; hf < 2; hf++) {
            int m = by * 128 + wm * 64 + mt * 16 + g + hf * 8;
            int b = m / NTOK, n = m - b * NTOK;
#pragma unroll
            for (int nt = 0; nt < 4; nt++) {
                int c = ncol0 + wn * 32 + nt * 8 + 2 * tig;
                int h = c >> 5, d = c & 31;
                float v0 = (acc[mt][nt][hf * 2 + 0] + bias[c]) * scale;
                float v1 = (acc[mt][nt][hf * 2 + 1] + bias[c + 1]) * scale;
                *(__half2*)(outp + ((((size_t)b * NHD + h) * NTOK + n) * HDIM + d)) =
                    __floats2half2_rn(v0, v1);
            }
        }
    }
}

// ---------------------------------------------------------------------------
// Kernel B: windowed attention, 8 windows per CTA sharing one bm tile.
// grid (512, 8); half = warp>>2 processes window 2*it+half, it=0..3, with
// double-buffered QKV stages. Softmax in exp2 domain (scales pre-folded).
// P in registers; PV results stored DIRECTLY to gmem (no smem staging).
// smem: 2 stages x 2 windows x 15360 + bm 17408 = 78848 -> 2 CTAs/SM.
// ---------------------------------------------------------------------------
#define WINBUF    15360    // Qs 5120 + Ks 5120 + Vs 5120
#define ATTN_SMEM 78848

__global__ __launch_bounds__(256, 2) void attn_kernel(float* __restrict__ out)
{
    extern __shared__ char smraw[];

    const int b0 = blockIdx.x;          // 0..511
    const int h  = blockIdx.y;
    const int w  = b0 & (NWIN - 1);

    const int tid = threadIdx.x;
    const int warp = tid >> 5, lane = tid & 31;
    const int half = warp >> 2;
    const int wl   = warp & 3;
    const int ht   = tid & 127;
    const int g = lane >> 2, tig = lane & 3;
    const int m0 = wl * 16;

    float* bmS = (float*)(smraw + 61440);   // 64 x 68 floats, shared all iters
    const float* bm = g_bm + ((size_t)(w * NHD + h)) * 64 * 68;

    auto loadWin = [&](int s, int it) {
        const int b = b0 + 512 * (2 * it + half);
        const size_t base = ((size_t)b * NHD + h) * (NTOK * HDIM);
        char* hb = smraw + s * 30720 + half * WINBUF;
        __half (*Qs)[40] = (__half(*)[40])(hb);
        __half (*Ks)[40] = (__half(*)[40])(hb + 5120);
        __half (*Vs)[40] = (__half(*)[40])(hb + 10240);
        const __half* qp = g_q + base;
        const __half* kp = g_k + base;
        const __half* vp = g_v + base;
#pragma unroll
        for (int c = ht; c < 256; c += 128) {
            int r = c >> 2, off = (c & 3) * 8;
            cp16(&Qs[r][off], qp + r * 32 + off);
        }
#pragma unroll
        for (int c = ht; c < 256; c += 128) {
            int r = c >> 2, off = (c & 3) * 8;
            cp16(&Ks[r][off], kp + r * 32 + off);
        }
#pragma unroll
        for (int c = ht; c < 256; c += 128) {
            int r = c >> 2, off = (c & 3) * 8;
            cp16(&Vs[r][off], vp + r * 32 + off);
        }
    };

    // Prologue: bm + stage0 (it=0) in group 0; stage1 (it=1) in group 1.
    for (int c = tid; c < 1088; c += 256)
        cp16((char*)bmS + c * 16, (const char*)bm + c * 16);
    loadWin(0, 0);
    asm volatile("cp.async.commit_group;" ::: "memory");
    loadWin(1, 1);
    asm volatile("cp.async.commit_group;" ::: "memory");

#pragma unroll
    for (int it = 0; it < 4; it++) {
        if (it < 3) asm volatile("cp.async.wait_group 1;" ::: "memory");
        else        asm volatile("cp.async.wait_group 0;" ::: "memory");
        __syncthreads();

        const int s = it & 1;
        char* hb = smraw + s * 30720 + half * WINBUF;
        __half (*Qs)[40] = (__half(*)[40])(hb);
        __half (*Ks)[40] = (__half(*)[40])(hb + 5120);
        __half (*Vs)[40] = (__half(*)[40])(hb + 10240);

        // --- scores = Q @ K^T (64 rows x 56 key cols: 7 n-tiles) ---
        float sc[7][4];
#pragma unroll
        for (int nt = 0; nt < 7; nt++)
#pragma unroll
            for (int e = 0; e < 4; e++) sc[nt][e] = 0.f;

#pragma unroll
        for (int ks = 0; ks < 2; ks++) {
            const int kc = ks * 16;
            uint32_t a[4];
            ldsm4(a, &Qs[m0 + (lane & 15)][kc + ((lane & 16) >> 1)]);
#pragma unroll
            for (int t = 0; t < 4; t++) {
                uint32_t bk_[4];
                ldsm4(bk_, &Ks[t * 16 + (lane & 7) + ((lane & 16) >> 1)][kc + (lane & 8)]);
                mma16816(sc[2 * t], a[0], a[1], a[2], a[3], bk_[0], bk_[1]);
                if (2 * t + 1 < 7)
                    mma16816(sc[2 * t + 1], a[0], a[1], a[2], a[3], bk_[2], bk_[3]);
            }
        }

        const int i0 = m0 + g, i1 = i0 + 8;
#pragma unroll
        for (int nt = 0; nt < 7; nt++) {
            int jc = nt * 8 + 2 * tig;
            float2 v0 = *(const float2*)&bmS[i0 * 68 + jc];
            float2 v1 = *(const float2*)&bmS[i1 * 68 + jc];
            sc[nt][0] += v0.x; sc[nt][1] += v0.y;
            sc[nt][2] += v1.x; sc[nt][3] += v1.y;
        }

        // --- softmax in exp2 domain ---
        float mx0 = -1e30f, mx1 = -1e30f;
#pragma unroll
        for (int nt = 0; nt < 7; nt++) {
            mx0 = fmaxf(mx0, fmaxf(sc[nt][0], sc[nt][1]));
            mx1 = fmaxf(mx1, fmaxf(sc[nt][2], sc[nt][3]));
        }
        mx0 = fmaxf(mx0, __shfl_xor_sync(0xffffffffu, mx0, 1));
        mx0 = fmaxf(mx0, __shfl_xor_sync(0xffffffffu, mx0, 2));
        mx1 = fmaxf(mx1, __shfl_xor_sync(0xffffffffu, mx1, 1));
        mx1 = fmaxf(mx1, __shfl_xor_sync(0xffffffffu, mx1, 2));

        float s0 = 0.f, s1 = 0.f;
#pragma unroll
        for (int nt = 0; nt < 7; nt++) {
            sc[nt][0] = exp2f(sc[nt][0] - mx0); s0 += sc[nt][0];
            sc[nt][1] = exp2f(sc[nt][1] - mx0); s0 += sc[nt][1];
            sc[nt][2] = exp2f(sc[nt][2] - mx1); s1 += sc[nt][2];
            sc[nt][3] = exp2f(sc[nt][3] - mx1); s1 += sc[nt][3];
        }
        s0 += __shfl_xor_sync(0xffffffffu, s0, 1);
        s0 += __shfl_xor_sync(0xffffffffu, s0, 2);
        s1 += __shfl_xor_sync(0xffffffffu, s1, 1);
        s1 += __shfl_xor_sync(0xffffffffu, s1, 2);
        const float r0 = 1.f / s0, r1 = 1.f / s1;

        // --- pack P fragments in registers ---
        uint32_t pa0[4], pa1[4], pa2[4], pa3[4];
#pragma unroll
        for (int kt = 0; kt < 4; kt++) {
            pa0[kt] = packh2(sc[2 * kt][0], sc[2 * kt][1]);
            pa1[kt] = packh2(sc[2 * kt][2], sc[2 * kt][3]);
            if (2 * kt + 1 < 7) {
                pa2[kt] = packh2(sc[2 * kt + 1][0], sc[2 * kt + 1][1]);
                pa3[kt] = packh2(sc[2 * kt + 1][2], sc[2 * kt + 1][3]);
            } else {
                pa2[kt] = 0u;
                pa3[kt] = 0u;
            }
        }

        // --- ctx = P @ V ---
        float o[4][4];
#pragma unroll
        for (int nt = 0; nt < 4; nt++)
#pragma unroll
            for (int e = 0; e < 4; e++) o[nt][e] = 0.f;

#pragma unroll
        for (int kt = 0; kt < 4; kt++) {
            const int kc = kt * 16;
            uint32_t bv0[4], bv1[4];
            ldsm4t(bv0, &Vs[kc + (lane & 15)][0  + ((lane & 16) >> 1)]);
            ldsm4t(bv1, &Vs[kc + (lane & 15)][16 + ((lane & 16) >> 1)]);
            mma16816(o[0], pa0[kt], pa1[kt], pa2[kt], pa3[kt], bv0[0], bv0[1]);
            mma16816(o[1], pa0[kt], pa1[kt], pa2[kt], pa3[kt], bv0[2], bv0[3]);
            mma16816(o[2], pa0[kt], pa1[kt], pa2[kt], pa3[kt], bv1[0], bv1[1]);
            mma16816(o[3], pa0[kt], pa1[kt], pa2[kt], pa3[kt], bv1[2], bv1[3]);
        }

        // All reads of stage s complete; refill with window it+2 FIRST so the
        // cp.asyncs overlap the output stores below.
        __syncthreads();
        if (it < 2) {
            loadWin(s, it + 2);
            asm volatile("cp.async.commit_group;" ::: "memory");
        }

        // --- direct global stores (predicated STG.64; no smem staging) ---
        const int b = b0 + 512 * (2 * it + half);
        float* ob = out + (size_t)b * NTOK * DMODEL + h * HDIM;
#pragma unroll
        for (int nt = 0; nt < 4; nt++) {
            int d = nt * 8 + 2 * tig;
            if (i0 < NTOK)
                *(float2*)(ob + (size_t)i0 * DMODEL + d) =
                    make_float2(o[nt][0] * r0, o[nt][1] * r0);
            if (i1 < NTOK)
                *(float2*)(ob + (size_t)i1 * DMODEL + d) =
                    make_float2(o[nt][2] * r1, o[nt][3] * r1);
        }
    }
}

extern "C" void kernel_launch(void* const* d_in, const int* in_sizes, int n_in,
                              void* d_out, int out_size)
{
    (void)in_sizes; (void)n_in; (void)out_size;
    const float* hidden = (const float*)d_in[0];
    const float* amask  = (const float*)d_in[1];
    const float* wq     = (const float*)d_in[2];
    const float* bq     = (const float*)d_in[3];
    const float* wk     = (const float*)d_in[4];
    const float* bk     = (const float*)d_in[5];
    const float* wv     = (const float*)d_in[6];
    const float* bv     = (const float*)d_in[7];
    const float* table  = (const float*)d_in[8];
    float* out = (float*)d_out;

    cudaFuncSetAttribute(qkv_kernel, cudaFuncAttributeMaxDynamicSharedMemorySize,
                         QKV_SMEM);
    cudaFuncSetAttribute(attn_kernel, cudaFuncAttributeMaxDynamicSharedMemorySize,
                         ATTN_SMEM);

    prep_all<<<51456, 256>>>(hidden, amask, table, wq, wk, wv);
    qkv_kernel<<<dim3(6, 1568), 256, QKV_SMEM>>>(bq, bk, bv);
    attn_kernel<<<dim3(512, NHD), 256, ATTN_SMEM>>>(out);
}

// round 15
// speedup vs baseline: 1.2093x; 1.0105x over previous
#include <cuda_runtime.h>
#include <cuda_fp16.h>
#include <cstdint>

#define NTOK   49
#define NHD    8
#define HDIM   32
#define DMODEL 256
#define NBATCH 4096
#define NWIN   64
#define MROWS  (NBATCH * NTOK)   // 200704
#define LOG2E  1.4426950408889634f

// fp16 scratch. +2048 halves padding: attn loads 64 padded rows per (b,h).
__device__ __half g_q[(size_t)NBATCH * NHD * NTOK * HDIM + 2048];
__device__ __half g_k[(size_t)NBATCH * NHD * NTOK * HDIM + 2048];
__device__ __half g_v[(size_t)NBATCH * NHD * NTOK * HDIM + 2048];
__device__ __half g_x[(size_t)MROWS * DMODEL];
__device__ __half g_w[3 * 256 * 256];           // [mat][n][k] (W transposed)
__device__ float  g_bm[NWIN * NHD * 64 * 68];   // (mask+bias)*log2e, padded

__device__ __forceinline__ void mma16816(float c[4],
                                         uint32_t a0, uint32_t a1, uint32_t a2, uint32_t a3,
                                         uint32_t b0, uint32_t b1) {
    asm volatile(
        "mma.sync.aligned.m16n8k16.row.col.f32.f16.f16.f32 "
        "{%0,%1,%2,%3}, {%4,%5,%6,%7}, {%8,%9}, {%0,%1,%2,%3};"
        : "+f"(c[0]), "+f"(c[1]), "+f"(c[2]), "+f"(c[3])
        : "r"(a0), "r"(a1), "r"(a2), "r"(a3), "r"(b0), "r"(b1));
}

__device__ __forceinline__ void ldsm4(uint32_t r[4], const void* p) {
    uint32_t a = (uint32_t)__cvta_generic_to_shared(p);
    asm volatile("ldmatrix.sync.aligned.m8n8.x4.shared.b16 {%0,%1,%2,%3}, [%4];"
                 : "=r"(r[0]), "=r"(r[1]), "=r"(r[2]), "=r"(r[3]) : "r"(a));
}

__device__ __forceinline__ void ldsm4t(uint32_t r[4], const void* p) {
    uint32_t a = (uint32_t)__cvta_generic_to_shared(p);
    asm volatile("ldmatrix.sync.aligned.m8n8.x4.trans.shared.b16 {%0,%1,%2,%3}, [%4];"
                 : "=r"(r[0]), "=r"(r[1]), "=r"(r[2]), "=r"(r[3]) : "r"(a));
}

__device__ __forceinline__ void cp16(void* s, const void* g) {
    uint32_t sa = (uint32_t)__cvta_generic_to_shared(s);
    asm volatile("cp.async.cg.shared.global [%0], [%1], 16;" :: "r"(sa), "l"(g));
}

__device__ __forceinline__ uint32_t packh2(float x, float y) {
    __half2 h = __floats2half2_rn(x, y);
    return *(uint32_t*)&h;
}

// ---------------------------------------------------------------------------
// prep_all: single launch for every precompute.
//   blocks [0, 12544)     : X fp32 -> fp16 (4 independent float4 per thread)
//   blocks [12544, 13056) : combined (mask+bias)*LOG2E  g_bm[w][h][64][68]
//   blocks [13056, 13824) : W transpose+convert g_w[mat][n][k]
// ---------------------------------------------------------------------------
__global__ __launch_bounds__(256) void prep_all(
    const float* __restrict__ X,
    const float* __restrict__ mask, const float* __restrict__ table,
    const float* __restrict__ wq, const float* __restrict__ wk,
    const float* __restrict__ wv)
{
    const int id = blockIdx.x;
    if (id < 12544) {
        const size_t base = (size_t)id * 1024 + threadIdx.x;
        float4 v[4];
#pragma unroll
        for (int j = 0; j < 4; j++)                 // 4 in-flight loads (MLP=4)
            v[j] = ((const float4*)X)[base + j * 256];
#pragma unroll
        for (int j = 0; j < 4; j++) {
            __half2* o = (__half2*)(g_x + (base + j * 256) * 4);
            o[0] = __floats2half2_rn(v[j].x, v[j].y);
            o[1] = __floats2half2_rn(v[j].z, v[j].w);
        }
    } else if (id < 13056) {
        const int bid = id - 12544;
        const int w = bid >> 3, h = bid & 7;
        float* dst = g_bm + ((size_t)(w * NHD + h)) * 64 * 68;
        for (int idx = threadIdx.x; idx < 64 * 68; idx += 256) {
            int i = idx / 68, j = idx - i * 68;
            float v;
            if (j >= NTOK)      v = -1e30f;
            else if (i >= NTOK) v = 0.f;
            else {
                int ih = i / 7, iw = i - ih * 7;
                int jh = j / 7, jw = j - jh * 7;
                int r = (ih - jh + 6) * 13 + (iw - jw + 6);
                v = (mask[((size_t)w * NTOK + i) * NTOK + j] + table[r * NHD + h])
                    * LOG2E;
            }
            dst[idx] = v;
        }
    } else {
        const int wid = id - 13056;
        const int mat = wid >> 8, k = wid & 255, n = threadIdx.x;
        const float* W = (mat == 0) ? wq : (mat == 1) ? wk : wv;
        g_w[((size_t)mat * 256 + n) * 256 + k] = __float2half_rn(W[k * 256 + n]);
    }
}

// ---------------------------------------------------------------------------
// Kernel A: QKV projection (round-9 config; measured 262us — the legacy-HMMA
// issue roofline; mainloop frozen). Q scale folds in LOG2E (exp2 softmax).
// ---------------------------------------------------------------------------
#define QKV_SMEM 73728

__global__ __launch_bounds__(256, 2) void qkv_kernel(
    const float* __restrict__ bq, const float* __restrict__ bk,
    const float* __restrict__ bv)
{
    extern __shared__ __half sm[];   // stage s: As at s*18432, Bs at +9216 (halves)

    const int bx = blockIdx.x, by = blockIdx.y;
    const int tid = threadIdx.x;
    const int warp = tid >> 5, lane = tid & 31;
    const int wm = warp & 1, wn = warp >> 1;
    const int g = lane >> 2, tig = lane & 3;

    const int mat   = bx >> 1;
    const int ncol0 = (bx & 1) * 128;
    const float* bias = (mat == 0) ? bq : (mat == 1) ? bk : bv;

    const __half* xrow  = g_x + (size_t)by * 128 * 256;
    const __half* wbase = g_w + ((size_t)mat * 256 + ncol0) * 256;

    auto loadStage = [&](int s, int kp) {
        __half* A = sm + s * 18432;
        __half* B = sm + s * 18432 + 9216;
        const __half* xs = xrow + kp * 64;
        const __half* ws = wbase + kp * 64;
#pragma unroll
        for (int c = tid; c < 1024; c += 256) {
            int r = c >> 3, off = (c & 7) * 8;
            cp16(A + r * 72 + off, xs + (size_t)r * 256 + off);
        }
#pragma unroll
        for (int c = tid; c < 1024; c += 256) {
            int r = c >> 3, off = (c & 7) * 8;
            cp16(B + r * 72 + off, ws + (size_t)r * 256 + off);
        }
        asm volatile("cp.async.commit_group;" ::: "memory");
    };

    loadStage(0, 0);
    loadStage(1, 1);

    float acc[4][4][4];
#pragma unroll
    for (int mt = 0; mt < 4; mt++)
#pragma unroll
        for (int nt = 0; nt < 4; nt++)
#pragma unroll
            for (int e = 0; e < 4; e++) acc[mt][nt][e] = 0.f;

    const int aRow = wm * 64 + (lane & 15);
    const int aCol = (lane & 16) >> 1;
    const int bRow = wn * 32 + (lane & 7) + ((lane & 16) >> 1);
    const int bCol = lane & 8;

#pragma unroll
    for (int kp = 0; kp < 4; kp++) {
        if (kp < 3) asm volatile("cp.async.wait_group 1;" ::: "memory");
        else        asm volatile("cp.async.wait_group 0;" ::: "memory");
        __syncthreads();

        const __half* A = sm + (kp & 1) * 18432;
        const __half* B = sm + (kp & 1) * 18432 + 9216;

#pragma unroll
        for (int ks = 0; ks < 4; ks++) {
            const int kc = ks * 16;
            uint32_t bf0[4], bf1[4];
            ldsm4(bf0, B + bRow * 72 + kc + bCol);
            ldsm4(bf1, B + (bRow + 16) * 72 + kc + bCol);
#pragma unroll
            for (int mt = 0; mt < 4; mt++) {
                uint32_t a[4];
                ldsm4(a, A + (aRow + mt * 16) * 72 + kc + aCol);
                mma16816(acc[mt][0], a[0], a[1], a[2], a[3], bf0[0], bf0[1]);
                mma16816(acc[mt][1], a[0], a[1], a[2], a[3], bf0[2], bf0[3]);
                mma16816(acc[mt][2], a[0], a[1], a[2], a[3], bf1[0], bf1[1]);
                mma16816(acc[mt][3], a[0], a[1], a[2], a[3], bf1[2], bf1[3]);
            }
        }

        if (kp < 2) {
            __syncthreads();
            loadStage(kp & 1, kp + 2);
        }
    }

    __half* outp = (mat == 0) ? g_q : (mat == 1) ? g_k : g_v;
    const float scale = (mat == 0) ? 0.17677669529663687f * LOG2E : 1.0f;
#pragma unroll
    for (int mt = 0; mt < 4; mt++) {
#pragma unroll
        for (int hf = 0; hf < 2; hf++) {
            int m = by * 128 + wm * 64 + mt * 16 + g + hf * 8;
            int b = m / NTOK, n = m - b * NTOK;
#pragma unroll
            for (int nt = 0; nt < 4; nt++) {
                int c = ncol0 + wn * 32 + nt * 8 + 2 * tig;
                int h = c >> 5, d = c & 31;
                float v0 = (acc[mt][nt][hf * 2 + 0] + bias[c]) * scale;
                float v1 = (acc[mt][nt][hf * 2 + 1] + bias[c + 1]) * scale;
                *(__half2*)(outp + ((((size_t)b * NHD + h) * NTOK + n) * HDIM + d)) =
                    __floats2half2_rn(v0, v1);
            }
        }
    }
}

// ---------------------------------------------------------------------------
// Kernel B: windowed attention, 8 windows per CTA sharing one bm tile.
// bm stored in smem with 64-float rows + rotation swizzle off=(j+4i)&63
// (same bank spread as the old 68-stride, 1KB smaller) -> ATTN_SMEM = 77824
// = 228KB/3 exactly -> 3 CTAs/SM (24 warps). Softmax in exp2 domain; P in
// registers; direct gmem stores.
// ---------------------------------------------------------------------------
#define WINBUF    15360    // Qs 5120 + Ks 5120 + Vs 5120
#define ATTN_SMEM 77824    // 2*2*15360 + 64*64*4

__global__ __launch_bounds__(256, 3) void attn_kernel(float* __restrict__ out)
{
    extern __shared__ char smraw[];

    const int b0 = blockIdx.x;          // 0..511
    const int h  = blockIdx.y;
    const int w  = b0 & (NWIN - 1);

    const int tid = threadIdx.x;
    const int warp = tid >> 5, lane = tid & 31;
    const int half = warp >> 2;
    const int wl   = warp & 3;
    const int ht   = tid & 127;
    const int g = lane >> 2, tig = lane & 3;
    const int m0 = wl * 16;

    float* bmS = (float*)(smraw + 61440);   // 64 rows x 64 floats, swizzled
    const float* bm = g_bm + ((size_t)(w * NHD + h)) * 64 * 68;

    auto loadWin = [&](int s, int it) {
        const int b = b0 + 512 * (2 * it + half);
        const size_t base = ((size_t)b * NHD + h) * (NTOK * HDIM);
        char* hb = smraw + s * 30720 + half * WINBUF;
        __half (*Qs)[40] = (__half(*)[40])(hb);
        __half (*Ks)[40] = (__half(*)[40])(hb + 5120);
        __half (*Vs)[40] = (__half(*)[40])(hb + 10240);
        const __half* qp = g_q + base;
        const __half* kp = g_k + base;
        const __half* vp = g_v + base;
#pragma unroll
        for (int c = ht; c < 256; c += 128) {
            int r = c >> 2, off = (c & 3) * 8;
            cp16(&Qs[r][off], qp + r * 32 + off);
        }
#pragma unroll
        for (int c = ht; c < 256; c += 128) {
            int r = c >> 2, off = (c & 3) * 8;
            cp16(&Ks[r][off], kp + r * 32 + off);
        }
#pragma unroll
        for (int c = ht; c < 256; c += 128) {
            int r = c >> 2, off = (c & 3) * 8;
            cp16(&Vs[r][off], vp + r * 32 + off);
        }
    };

    // Prologue: bm (swizzled copy of cols 0..63) + stage0; then stage1.
    for (int c = tid; c < 1024; c += 256) {
        int i = c >> 4, c4 = (c & 15) * 4;
        int dst = i * 64 + ((c4 + 4 * i) & 63);
        cp16((char*)(bmS + dst), (const char*)(bm + i * 68 + c4));
    }
    loadWin(0, 0);
    asm volatile("cp.async.commit_group;" ::: "memory");
    loadWin(1, 1);
    asm volatile("cp.async.commit_group;" ::: "memory");

#pragma unroll
    for (int it = 0; it < 4; it++) {
        if (it < 3) asm volatile("cp.async.wait_group 1;" ::: "memory");
        else        asm volatile("cp.async.wait_group 0;" ::: "memory");
        __syncthreads();

        const int s = it & 1;
        char* hb = smraw + s * 30720 + half * WINBUF;
        __half (*Qs)[40] = (__half(*)[40])(hb);
        __half (*Ks)[40] = (__half(*)[40])(hb + 5120);
        __half (*Vs)[40] = (__half(*)[40])(hb + 10240);

        // --- scores = Q @ K^T (64 rows x 56 key cols: 7 n-tiles) ---
        float sc[7][4];
#pragma unroll
        for (int nt = 0; nt < 7; nt++)
#pragma unroll
            for (int e = 0; e < 4; e++) sc[nt][e] = 0.f;

#pragma unroll
        for (int ks = 0; ks < 2; ks++) {
            const int kc = ks * 16;
            uint32_t a[4];
            ldsm4(a, &Qs[m0 + (lane & 15)][kc + ((lane & 16) >> 1)]);
#pragma unroll
            for (int t = 0; t < 4; t++) {
                uint32_t bk_[4];
                ldsm4(bk_, &Ks[t * 16 + (lane & 7) + ((lane & 16) >> 1)][kc + (lane & 8)]);
                mma16816(sc[2 * t], a[0], a[1], a[2], a[3], bk_[0], bk_[1]);
                if (2 * t + 1 < 7)
                    mma16816(sc[2 * t + 1], a[0], a[1], a[2], a[3], bk_[2], bk_[3]);
            }
        }

        const int i0 = m0 + g, i1 = i0 + 8;
#pragma unroll
        for (int nt = 0; nt < 7; nt++) {
            int jc = nt * 8 + 2 * tig;
            float2 v0 = *(const float2*)&bmS[i0 * 64 + ((jc + 4 * i0) & 63)];
            float2 v1 = *(const float2*)&bmS[i1 * 64 + ((jc + 4 * i1) & 63)];
            sc[nt][0] += v0.x; sc[nt][1] += v0.y;
            sc[nt][2] += v1.x; sc[nt][3] += v1.y;
        }

        // --- softmax in exp2 domain ---
        float mx0 = -1e30f, mx1 = -1e30f;
#pragma unroll
        for (int nt = 0; nt < 7; nt++) {
            mx0 = fmaxf(mx0, fmaxf(sc[nt][0], sc[nt][1]));
            mx1 = fmaxf(mx1, fmaxf(sc[nt][2], sc[nt][3]));
        }
        mx0 = fmaxf(mx0, __shfl_xor_sync(0xffffffffu, mx0, 1));
        mx0 = fmaxf(mx0, __shfl_xor_sync(0xffffffffu, mx0, 2));
        mx1 = fmaxf(mx1, __shfl_xor_sync(0xffffffffu, mx1, 1));
        mx1 = fmaxf(mx1, __shfl_xor_sync(0xffffffffu, mx1, 2));

        float s0 = 0.f, s1 = 0.f;
#pragma unroll
        for (int nt = 0; nt < 7; nt++) {
            sc[nt][0] = exp2f(sc[nt][0] - mx0); s0 += sc[nt][0];
            sc[nt][1] = exp2f(sc[nt][1] - mx0); s0 += sc[nt][1];
            sc[nt][2] = exp2f(sc[nt][2] - mx1); s1 += sc[nt][2];
            sc[nt][3] = exp2f(sc[nt][3] - mx1); s1 += sc[nt][3];
        }
        s0 += __shfl_xor_sync(0xffffffffu, s0, 1);
        s0 += __shfl_xor_sync(0xffffffffu, s0, 2);
        s1 += __shfl_xor_sync(0xffffffffu, s1, 1);
        s1 += __shfl_xor_sync(0xffffffffu, s1, 2);
        const float r0 = 1.f / s0, r1 = 1.f / s1;

        // --- pack P fragments in registers ---
        uint32_t pa0[4], pa1[4], pa2[4], pa3[4];
#pragma unroll
        for (int kt = 0; kt < 4; kt++) {
            pa0[kt] = packh2(sc[2 * kt][0], sc[2 * kt][1]);
            pa1[kt] = packh2(sc[2 * kt][2], sc[2 * kt][3]);
            if (2 * kt + 1 < 7) {
                pa2[kt] = packh2(sc[2 * kt + 1][0], sc[2 * kt + 1][1]);
                pa3[kt] = packh2(sc[2 * kt + 1][2], sc[2 * kt + 1][3]);
            } else {
                pa2[kt] = 0u;
                pa3[kt] = 0u;
            }
        }

        // --- ctx = P @ V ---
        float o[4][4];
#pragma unroll
        for (int nt = 0; nt < 4; nt++)
#pragma unroll
            for (int e = 0; e < 4; e++) o[nt][e] = 0.f;

#pragma unroll
        for (int kt = 0; kt < 4; kt++) {
            const int kc = kt * 16;
            uint32_t bv0[4], bv1[4];
            ldsm4t(bv0, &Vs[kc + (lane & 15)][0  + ((lane & 16) >> 1)]);
            ldsm4t(bv1, &Vs[kc + (lane & 15)][16 + ((lane & 16) >> 1)]);
            mma16816(o[0], pa0[kt], pa1[kt], pa2[kt], pa3[kt], bv0[0], bv0[1]);
            mma16816(o[1], pa0[kt], pa1[kt], pa2[kt], pa3[kt], bv0[2], bv0[3]);
            mma16816(o[2], pa0[kt], pa1[kt], pa2[kt], pa3[kt], bv1[0], bv1[1]);
            mma16816(o[3], pa0[kt], pa1[kt], pa2[kt], pa3[kt], bv1[2], bv1[3]);
        }

        // All reads of stage s complete; refill with window it+2 FIRST so the
        // cp.asyncs overlap the output stores below.
        __syncthreads();
        if (it < 2) {
            loadWin(s, it + 2);
            asm volatile("cp.async.commit_group;" ::: "memory");
        }

        // --- direct global stores ---
        const int b = b0 + 512 * (2 * it + half);
        float* ob = out + (size_t)b * NTOK * DMODEL + h * HDIM;
#pragma unroll
        for (int nt = 0; nt < 4; nt++) {
            int d = nt * 8 + 2 * tig;
            if (i0 < NTOK)
                *(float2*)(ob + (size_t)i0 * DMODEL + d) =
                    make_float2(o[nt][0] * r0, o[nt][1] * r0);
            if (i1 < NTOK)
                *(float2*)(ob + (size_t)i1 * DMODEL + d) =
                    make_float2(o[nt][2] * r1, o[nt][3] * r1);
        }
    }
}

extern "C" void kernel_launch(void* const* d_in, const int* in_sizes, int n_in,
                              void* d_out, int out_size)
{
    (void)in_sizes; (void)n_in; (void)out_size;
    const float* hidden = (const float*)d_in[0];
    const float* amask  = (const float*)d_in[1];
    const float* wq     = (const float*)d_in[2];
    const float* bq     = (const float*)d_in[3];
    const float* wk     = (const float*)d_in[4];
    const float* bk     = (const float*)d_in[5];
    const float* wv     = (const float*)d_in[6];
    const float* bv     = (const float*)d_in[7];
    const float* table  = (const float*)d_in[8];
    float* out = (float*)d_out;

    cudaFuncSetAttribute(qkv_kernel, cudaFuncAttributeMaxDynamicSharedMemorySize,
                         QKV_SMEM);
    cudaFuncSetAttribute(attn_kernel, cudaFuncAttributeMaxDynamicSharedMemorySize,
                         ATTN_SMEM);

    prep_all<<<13824, 256>>>(hidden, amask, table, wq, wk, wv);
    qkv_kernel<<<dim3(6, 1568), 256, QKV_SMEM>>>(bq, bk, bv);
    attn_kernel<<<dim3(512, NHD), 256, ATTN_SMEM>>>(out);
}

// round 16
// speedup vs baseline: 1.2184x; 1.0076x over previous
#include <cuda_runtime.h>
#include <cuda_fp16.h>
#include <cstdint>

#define NTOK   49
#define NHD    8
#define HDIM   32
#define DMODEL 256
#define NBATCH 4096
#define NWIN   64
#define MROWS  (NBATCH * NTOK)   // 200704
#define LOG2E  1.4426950408889634f

// fp16 scratch. +2048 halves padding: attn loads 64 padded rows per (b,h).
__device__ __half g_q[(size_t)NBATCH * NHD * NTOK * HDIM + 2048];
__device__ __half g_k[(size_t)NBATCH * NHD * NTOK * HDIM + 2048];
__device__ __half g_v[(size_t)NBATCH * NHD * NTOK * HDIM + 2048];
__device__ __half g_x[(size_t)MROWS * DMODEL];
__device__ __half g_w[3 * 256 * 256];           // [mat][n][k] (W transposed)
__device__ float  g_bm[NWIN * NHD * 64 * 68];   // (mask+bias)*log2e, padded

__device__ __forceinline__ void mma16816(float c[4],
                                         uint32_t a0, uint32_t a1, uint32_t a2, uint32_t a3,
                                         uint32_t b0, uint32_t b1) {
    asm volatile(
        "mma.sync.aligned.m16n8k16.row.col.f32.f16.f16.f32 "
        "{%0,%1,%2,%3}, {%4,%5,%6,%7}, {%8,%9}, {%0,%1,%2,%3};"
        : "+f"(c[0]), "+f"(c[1]), "+f"(c[2]), "+f"(c[3])
        : "r"(a0), "r"(a1), "r"(a2), "r"(a3), "r"(b0), "r"(b1));
}

__device__ __forceinline__ void ldsm4(uint32_t r[4], const void* p) {
    uint32_t a = (uint32_t)__cvta_generic_to_shared(p);
    asm volatile("ldmatrix.sync.aligned.m8n8.x4.shared.b16 {%0,%1,%2,%3}, [%4];"
                 : "=r"(r[0]), "=r"(r[1]), "=r"(r[2]), "=r"(r[3]) : "r"(a));
}

__device__ __forceinline__ void ldsm4t(uint32_t r[4], const void* p) {
    uint32_t a = (uint32_t)__cvta_generic_to_shared(p);
    asm volatile("ldmatrix.sync.aligned.m8n8.x4.trans.shared.b16 {%0,%1,%2,%3}, [%4];"
                 : "=r"(r[0]), "=r"(r[1]), "=r"(r[2]), "=r"(r[3]) : "r"(a));
}

__device__ __forceinline__ void cp16(void* s, const void* g) {
    uint32_t sa = (uint32_t)__cvta_generic_to_shared(s);
    asm volatile("cp.async.cg.shared.global [%0], [%1], 16;" :: "r"(sa), "l"(g));
}

__device__ __forceinline__ uint32_t packh2(float x, float y) {
    __half2 h = __floats2half2_rn(x, y);
    return *(uint32_t*)&h;
}

// ---------------------------------------------------------------------------
// prep_all (measured 46.4us, 74% DRAM — near floor):
//   blocks [0, 12544)     : X fp32 -> fp16 (4 independent float4 per thread)
//   blocks [12544, 13056) : combined (mask+bias)*LOG2E  g_bm[w][h][64][68]
//   blocks [13056, 13824) : W transpose+convert g_w[mat][n][k]
// ---------------------------------------------------------------------------
__global__ __launch_bounds__(256) void prep_all(
    const float* __restrict__ X,
    const float* __restrict__ mask, const float* __restrict__ table,
    const float* __restrict__ wq, const float* __restrict__ wk,
    const float* __restrict__ wv)
{
    const int id = blockIdx.x;
    if (id < 12544) {
        const size_t base = (size_t)id * 1024 + threadIdx.x;
        float4 v[4];
#pragma unroll
        for (int j = 0; j < 4; j++)                 // 4 in-flight loads (MLP=4)
            v[j] = ((const float4*)X)[base + j * 256];
#pragma unroll
        for (int j = 0; j < 4; j++) {
            __half2* o = (__half2*)(g_x + (base + j * 256) * 4);
            o[0] = __floats2half2_rn(v[j].x, v[j].y);
            o[1] = __floats2half2_rn(v[j].z, v[j].w);
        }
    } else if (id < 13056) {
        const int bid = id - 12544;
        const int w = bid >> 3, h = bid & 7;
        float* dst = g_bm + ((size_t)(w * NHD + h)) * 64 * 68;
        for (int idx = threadIdx.x; idx < 64 * 68; idx += 256) {
            int i = idx / 68, j = idx - i * 68;
            float v;
            if (j >= NTOK)      v = -1e30f;
            else if (i >= NTOK) v = 0.f;
            else {
                int ih = i / 7, iw = i - ih * 7;
                int jh = j / 7, jw = j - jh * 7;
                int r = (ih - jh + 6) * 13 + (iw - jw + 6);
                v = (mask[((size_t)w * NTOK + i) * NTOK + j] + table[r * NHD + h])
                    * LOG2E;
            }
            dst[idx] = v;
        }
    } else {
        const int wid = id - 13056;
        const int mat = wid >> 8, k = wid & 255, n = threadIdx.x;
        const float* W = (mat == 0) ? wq : (mat == 1) ? wk : wv;
        g_w[((size_t)mat * 256 + n) * 256 + k] = __float2half_rn(W[k * 256 + n]);
    }
}

// ---------------------------------------------------------------------------
// Kernel A: QKV projection (round-9 config; measured 262us — the legacy-HMMA
// issue roofline; mainloop frozen). Q scale folds in LOG2E (exp2 softmax).
// ---------------------------------------------------------------------------
#define QKV_SMEM 73728

__global__ __launch_bounds__(256, 2) void qkv_kernel(
    const float* __restrict__ bq, const float* __restrict__ bk,
    const float* __restrict__ bv)
{
    extern __shared__ __half sm[];   // stage s: As at s*18432, Bs at +9216 (halves)

    const int bx = blockIdx.x, by = blockIdx.y;
    const int tid = threadIdx.x;
    const int warp = tid >> 5, lane = tid & 31;
    const int wm = warp & 1, wn = warp >> 1;
    const int g = lane >> 2, tig = lane & 3;

    const int mat   = bx >> 1;
    const int ncol0 = (bx & 1) * 128;
    const float* bias = (mat == 0) ? bq : (mat == 1) ? bk : bv;

    const __half* xrow  = g_x + (size_t)by * 128 * 256;
    const __half* wbase = g_w + ((size_t)mat * 256 + ncol0) * 256;

    auto loadStage = [&](int s, int kp) {
        __half* A = sm + s * 18432;
        __half* B = sm + s * 18432 + 9216;
        const __half* xs = xrow + kp * 64;
        const __half* ws = wbase + kp * 64;
#pragma unroll
        for (int c = tid; c < 1024; c += 256) {
            int r = c >> 3, off = (c & 7) * 8;
            cp16(A + r * 72 + off, xs + (size_t)r * 256 + off);
        }
#pragma unroll
        for (int c = tid; c < 1024; c += 256) {
            int r = c >> 3, off = (c & 7) * 8;
            cp16(B + r * 72 + off, ws + (size_t)r * 256 + off);
        }
        asm volatile("cp.async.commit_group;" ::: "memory");
    };

    loadStage(0, 0);
    loadStage(1, 1);

    float acc[4][4][4];
#pragma unroll
    for (int mt = 0; mt < 4; mt++)
#pragma unroll
        for (int nt = 0; nt < 4; nt++)
#pragma unroll
            for (int e = 0; e < 4; e++) acc[mt][nt][e] = 0.f;

    const int aRow = wm * 64 + (lane & 15);
    const int aCol = (lane & 16) >> 1;
    const int bRow = wn * 32 + (lane & 7) + ((lane & 16) >> 1);
    const int bCol = lane & 8;

#pragma unroll
    for (int kp = 0; kp < 4; kp++) {
        if (kp < 3) asm volatile("cp.async.wait_group 1;" ::: "memory");
        else        asm volatile("cp.async.wait_group 0;" ::: "memory");
        __syncthreads();

        const __half* A = sm + (kp & 1) * 18432;
        const __half* B = sm + (kp & 1) * 18432 + 9216;

#pragma unroll
        for (int ks = 0; ks < 4; ks++) {
            const int kc = ks * 16;
            uint32_t bf0[4], bf1[4];
            ldsm4(bf0, B + bRow * 72 + kc + bCol);
            ldsm4(bf1, B + (bRow + 16) * 72 + kc + bCol);
#pragma unroll
            for (int mt = 0; mt < 4; mt++) {
                uint32_t a[4];
                ldsm4(a, A + (aRow + mt * 16) * 72 + kc + aCol);
                mma16816(acc[mt][0], a[0], a[1], a[2], a[3], bf0[0], bf0[1]);
                mma16816(acc[mt][1], a[0], a[1], a[2], a[3], bf0[2], bf0[3]);
                mma16816(acc[mt][2], a[0], a[1], a[2], a[3], bf1[0], bf1[1]);
                mma16816(acc[mt][3], a[0], a[1], a[2], a[3], bf1[2], bf1[3]);
            }
        }

        if (kp < 2) {
            __syncthreads();
            loadStage(kp & 1, kp + 2);
        }
    }

    __half* outp = (mat == 0) ? g_q : (mat == 1) ? g_k : g_v;
    const float scale = (mat == 0) ? 0.17677669529663687f * LOG2E : 1.0f;
#pragma unroll
    for (int mt = 0; mt < 4; mt++) {
#pragma unroll
        for (int hf = 0; hf < 2; hf++) {
            int m = by * 128 + wm * 64 + mt * 16 + g + hf * 8;
            int b = m / NTOK, n = m - b * NTOK;
#pragma unroll
            for (int nt = 0; nt < 4; nt++) {
                int c = ncol0 + wn * 32 + nt * 8 + 2 * tig;
                int h = c >> 5, d = c & 31;
                float v0 = (acc[mt][nt][hf * 2 + 0] + bias[c]) * scale;
                float v1 = (acc[mt][nt][hf * 2 + 1] + bias[c + 1]) * scale;
                *(__half2*)(outp + ((((size_t)b * NHD + h) * NTOK + n) * HDIM + d)) =
                    __floats2half2_rn(v0, v1);
            }
        }
    }
}

// ---------------------------------------------------------------------------
// Kernel B: windowed attention, 8 windows per CTA sharing one bm tile.
// 2 CTAs/SM (128 regs, NO spills — 3-CTA variant measured ~8us slower from
// the 85-reg cap). bm in smem: 64-float rows + rotation swizzle (j+4i)&63.
// Softmax in exp2 domain; P in registers; direct gmem stores.
// ---------------------------------------------------------------------------
#define WINBUF    15360    // Qs 5120 + Ks 5120 + Vs 5120
#define ATTN_SMEM 77824    // 2*2*15360 + 64*64*4

__global__ __launch_bounds__(256, 2) void attn_kernel(float* __restrict__ out)
{
    extern __shared__ char smraw[];

    const int b0 = blockIdx.x;          // 0..511
    const int h  = blockIdx.y;
    const int w  = b0 & (NWIN - 1);

    const int tid = threadIdx.x;
    const int warp = tid >> 5, lane = tid & 31;
    const int half = warp >> 2;
    const int wl   = warp & 3;
    const int ht   = tid & 127;
    const int g = lane >> 2, tig = lane & 3;
    const int m0 = wl * 16;

    float* bmS = (float*)(smraw + 61440);   // 64 rows x 64 floats, swizzled
    const float* bm = g_bm + ((size_t)(w * NHD + h)) * 64 * 68;

    auto loadWin = [&](int s, int it) {
        const int b = b0 + 512 * (2 * it + half);
        const size_t base = ((size_t)b * NHD + h) * (NTOK * HDIM);
        char* hb = smraw + s * 30720 + half * WINBUF;
        __half (*Qs)[40] = (__half(*)[40])(hb);
        __half (*Ks)[40] = (__half(*)[40])(hb + 5120);
        __half (*Vs)[40] = (__half(*)[40])(hb + 10240);
        const __half* qp = g_q + base;
        const __half* kp = g_k + base;
        const __half* vp = g_v + base;
#pragma unroll
        for (int c = ht; c < 256; c += 128) {
            int r = c >> 2, off = (c & 3) * 8;
            cp16(&Qs[r][off], qp + r * 32 + off);
        }
#pragma unroll
        for (int c = ht; c < 256; c += 128) {
            int r = c >> 2, off = (c & 3) * 8;
            cp16(&Ks[r][off], kp + r * 32 + off);
        }
#pragma unroll
        for (int c = ht; c < 256; c += 128) {
            int r = c >> 2, off = (c & 3) * 8;
            cp16(&Vs[r][off], vp + r * 32 + off);
        }
    };

    // Prologue: bm (swizzled copy of cols 0..63) + stage0; then stage1.
    for (int c = tid; c < 1024; c += 256) {
        int i = c >> 4, c4 = (c & 15) * 4;
        int dst = i * 64 + ((c4 + 4 * i) & 63);
        cp16((char*)(bmS + dst), (const char*)(bm + i * 68 + c4));
    }
    loadWin(0, 0);
    asm volatile("cp.async.commit_group;" ::: "memory");
    loadWin(1, 1);
    asm volatile("cp.async.commit_group;" ::: "memory");

#pragma unroll
    for (int it = 0; it < 4; it++) {
        if (it < 3) asm volatile("cp.async.wait_group 1;" ::: "memory");
        else        asm volatile("cp.async.wait_group 0;" ::: "memory");
        __syncthreads();

        const int s = it & 1;
        char* hb = smraw + s * 30720 + half * WINBUF;
        __half (*Qs)[40] = (__half(*)[40])(hb);
        __half (*Ks)[40] = (__half(*)[40])(hb + 5120);
        __half (*Vs)[40] = (__half(*)[40])(hb + 10240);

        // --- scores = Q @ K^T (64 rows x 56 key cols: 7 n-tiles) ---
        float sc[7][4];
#pragma unroll
        for (int nt = 0; nt < 7; nt++)
#pragma unroll
            for (int e = 0; e < 4; e++) sc[nt][e] = 0.f;

#pragma unroll
        for (int ks = 0; ks < 2; ks++) {
            const int kc = ks * 16;
            uint32_t a[4];
            ldsm4(a, &Qs[m0 + (lane & 15)][kc + ((lane & 16) >> 1)]);
#pragma unroll
            for (int t = 0; t < 4; t++) {
                uint32_t bk_[4];
                ldsm4(bk_, &Ks[t * 16 + (lane & 7) + ((lane & 16) >> 1)][kc + (lane & 8)]);
                mma16816(sc[2 * t], a[0], a[1], a[2], a[3], bk_[0], bk_[1]);
                if (2 * t + 1 < 7)
                    mma16816(sc[2 * t + 1], a[0], a[1], a[2], a[3], bk_[2], bk_[3]);
            }
        }

        const int i0 = m0 + g, i1 = i0 + 8;
#pragma unroll
        for (int nt = 0; nt < 7; nt++) {
            int jc = nt * 8 + 2 * tig;
            float2 v0 = *(const float2*)&bmS[i0 * 64 + ((jc + 4 * i0) & 63)];
            float2 v1 = *(const float2*)&bmS[i1 * 64 + ((jc + 4 * i1) & 63)];
            sc[nt][0] += v0.x; sc[nt][1] += v0.y;
            sc[nt][2] += v1.x; sc[nt][3] += v1.y;
        }

        // --- softmax in exp2 domain ---
        float mx0 = -1e30f, mx1 = -1e30f;
#pragma unroll
        for (int nt = 0; nt < 7; nt++) {
            mx0 = fmaxf(mx0, fmaxf(sc[nt][0], sc[nt][1]));
            mx1 = fmaxf(mx1, fmaxf(sc[nt][2], sc[nt][3]));
        }
        mx0 = fmaxf(mx0, __shfl_xor_sync(0xffffffffu, mx0, 1));
        mx0 = fmaxf(mx0, __shfl_xor_sync(0xffffffffu, mx0, 2));
        mx1 = fmaxf(mx1, __shfl_xor_sync(0xffffffffu, mx1, 1));
        mx1 = fmaxf(mx1, __shfl_xor_sync(0xffffffffu, mx1, 2));

        float s0 = 0.f, s1 = 0.f;
#pragma unroll
        for (int nt = 0; nt < 7; nt++) {
            sc[nt][0] = exp2f(sc[nt][0] - mx0); s0 += sc[nt][0];
            sc[nt][1] = exp2f(sc[nt][1] - mx0); s0 += sc[nt][1];
            sc[nt][2] = exp2f(sc[nt][2] - mx1); s1 += sc[nt][2];
            sc[nt][3] = exp2f(sc[nt][3] - mx1); s1 += sc[nt][3];
        }
        s0 += __shfl_xor_sync(0xffffffffu, s0, 1);
        s0 += __shfl_xor_sync(0xffffffffu, s0, 2);
        s1 += __shfl_xor_sync(0xffffffffu, s1, 1);
        s1 += __shfl_xor_sync(0xffffffffu, s1, 2);
        const float r0 = 1.f / s0, r1 = 1.f / s1;

        // --- pack P fragments in registers ---
        uint32_t pa0[4], pa1[4], pa2[4], pa3[4];
#pragma unroll
        for (int kt = 0; kt < 4; kt++) {
            pa0[kt] = packh2(sc[2 * kt][0], sc[2 * kt][1]);
            pa1[kt] = packh2(sc[2 * kt][2], sc[2 * kt][3]);
            if (2 * kt + 1 < 7) {
                pa2[kt] = packh2(sc[2 * kt + 1][0], sc[2 * kt + 1][1]);
                pa3[kt] = packh2(sc[2 * kt + 1][2], sc[2 * kt + 1][3]);
            } else {
                pa2[kt] = 0u;
                pa3[kt] = 0u;
            }
        }

        // --- ctx = P @ V ---
        float o[4][4];
#pragma unroll
        for (int nt = 0; nt < 4; nt++)
#pragma unroll
            for (int e = 0; e < 4; e++) o[nt][e] = 0.f;

#pragma unroll
        for (int kt = 0; kt < 4; kt++) {
            const int kc = kt * 16;
            uint32_t bv0[4], bv1[4];
            ldsm4t(bv0, &Vs[kc + (lane & 15)][0  + ((lane & 16) >> 1)]);
            ldsm4t(bv1, &Vs[kc + (lane & 15)][16 + ((lane & 16) >> 1)]);
            mma16816(o[0], pa0[kt], pa1[kt], pa2[kt], pa3[kt], bv0[0], bv0[1]);
            mma16816(o[1], pa0[kt], pa1[kt], pa2[kt], pa3[kt], bv0[2], bv0[3]);
            mma16816(o[2], pa0[kt], pa1[kt], pa2[kt], pa3[kt], bv1[0], bv1[1]);
            mma16816(o[3], pa0[kt], pa1[kt], pa2[kt], pa3[kt], bv1[2], bv1[3]);
        }

        // All reads of stage s complete; refill with window it+2 FIRST so the
        // cp.asyncs overlap the output stores below.
        __syncthreads();
        if (it < 2) {
            loadWin(s, it + 2);
            asm volatile("cp.async.commit_group;" ::: "memory");
        }

        // --- direct global stores ---
        const int b = b0 + 512 * (2 * it + half);
        float* ob = out + (size_t)b * NTOK * DMODEL + h * HDIM;
#pragma unroll
        for (int nt = 0; nt < 4; nt++) {
            int d = nt * 8 + 2 * tig;
            if (i0 < NTOK)
                *(float2*)(ob + (size_t)i0 * DMODEL + d) =
                    make_float2(o[nt][0] * r0, o[nt][1] * r0);
            if (i1 < NTOK)
                *(float2*)(ob + (size_t)i1 * DMODEL + d) =
                    make_float2(o[nt][2] * r1, o[nt][3] * r1);
        }
    }
}

extern "C" void kernel_launch(void* const* d_in, const int* in_sizes, int n_in,
                              void* d_out, int out_size)
{
    (void)in_sizes; (void)n_in; (void)out_size;
    const float* hidden = (const float*)d_in[0];
    const float* amask  = (const float*)d_in[1];
    const float* wq     = (const float*)d_in[2];
    const float* bq     = (const float*)d_in[3];
    const float* wk     = (const float*)d_in[4];
    const float* bk     = (const float*)d_in[5];
    const float* wv     = (const float*)d_in[6];
    const float* bv     = (const float*)d_in[7];
    const float* table  = (const float*)d_in[8];
    float* out = (float*)d_out;

    cudaFuncSetAttribute(qkv_kernel, cudaFuncAttributeMaxDynamicSharedMemorySize,
                         QKV_SMEM);
    cudaFuncSetAttribute(attn_kernel, cudaFuncAttributeMaxDynamicSharedMemorySize,
                         ATTN_SMEM);

    prep_all<<<13824, 256>>>(hidden, amask, table, wq, wk, wv);
    qkv_kernel<<<dim3(6, 1568), 256, QKV_SMEM>>>(bq, bk, bv);
    attn_kernel<<<dim3(512, NHD), 256, ATTN_SMEM>>>(out);
}

// round 17
// speedup vs baseline: 1.2344x; 1.0131x over previous
#include <cuda_runtime.h>
#include <cuda_fp16.h>
#include <cstdint>

#define NTOK   49
#define NHD    8
#define HDIM   32
#define DMODEL 256
#define NBATCH 4096
#define NWIN   64
#define MROWS  (NBATCH * NTOK)   // 200704
#define LOG2E  1.4426950408889634f

// fp16 scratch. +2048 halves padding: attn loads 64 padded rows per (b,h).
__device__ __half g_q[(size_t)NBATCH * NHD * NTOK * HDIM + 2048];
__device__ __half g_k[(size_t)NBATCH * NHD * NTOK * HDIM + 2048];
__device__ __half g_v[(size_t)NBATCH * NHD * NTOK * HDIM + 2048];
__device__ __half g_x[(size_t)MROWS * DMODEL];
__device__ __half g_w[3 * 256 * 256];           // [mat][n][k] (W transposed)
__device__ float  g_bm[NWIN * NHD * 64 * 68];   // (mask+bias)*log2e, padded

__device__ __forceinline__ void mma16816(float c[4],
                                         uint32_t a0, uint32_t a1, uint32_t a2, uint32_t a3,
                                         uint32_t b0, uint32_t b1) {
    asm volatile(
        "mma.sync.aligned.m16n8k16.row.col.f32.f16.f16.f32 "
        "{%0,%1,%2,%3}, {%4,%5,%6,%7}, {%8,%9}, {%0,%1,%2,%3};"
        : "+f"(c[0]), "+f"(c[1]), "+f"(c[2]), "+f"(c[3])
        : "r"(a0), "r"(a1), "r"(a2), "r"(a3), "r"(b0), "r"(b1));
}

__device__ __forceinline__ void ldsm4(uint32_t r[4], const void* p) {
    uint32_t a = (uint32_t)__cvta_generic_to_shared(p);
    asm volatile("ldmatrix.sync.aligned.m8n8.x4.shared.b16 {%0,%1,%2,%3}, [%4];"
                 : "=r"(r[0]), "=r"(r[1]), "=r"(r[2]), "=r"(r[3]) : "r"(a));
}

__device__ __forceinline__ void ldsm4t(uint32_t r[4], const void* p) {
    uint32_t a = (uint32_t)__cvta_generic_to_shared(p);
    asm volatile("ldmatrix.sync.aligned.m8n8.x4.trans.shared.b16 {%0,%1,%2,%3}, [%4];"
                 : "=r"(r[0]), "=r"(r[1]), "=r"(r[2]), "=r"(r[3]) : "r"(a));
}

__device__ __forceinline__ void cp16(void* s, const void* g) {
    uint32_t sa = (uint32_t)__cvta_generic_to_shared(s);
    asm volatile("cp.async.cg.shared.global [%0], [%1], 16;" :: "r"(sa), "l"(g));
}

// Packed half2 exp2: cvt two fp32 to f16x2 (ALU), one MUFU ex2 on the pair.
// lo = exp2(a), hi = exp2(b).
__device__ __forceinline__ uint32_t ex2h2(float a, float b) {
    uint32_t hv, r;
    asm("cvt.rn.f16x2.f32 %0, %2, %1;" : "=r"(hv) : "f"(a), "f"(b));
    asm("ex2.approx.f16x2 %0, %1;" : "=r"(r) : "r"(hv));
    return r;
}

// ---------------------------------------------------------------------------
// prep_all (measured ~47us, ~72% DRAM — near floor):
//   blocks [0, 12544)     : X fp32 -> fp16 (4 independent float4 per thread)
//   blocks [12544, 13056) : combined (mask+bias)*LOG2E  g_bm[w][h][64][68]
//   blocks [13056, 13824) : W transpose+convert g_w[mat][n][k]
// ---------------------------------------------------------------------------
__global__ __launch_bounds__(256) void prep_all(
    const float* __restrict__ X,
    const float* __restrict__ mask, const float* __restrict__ table,
    const float* __restrict__ wq, const float* __restrict__ wk,
    const float* __restrict__ wv)
{
    const int id = blockIdx.x;
    if (id < 12544) {
        const size_t base = (size_t)id * 1024 + threadIdx.x;
        float4 v[4];
#pragma unroll
        for (int j = 0; j < 4; j++)
            v[j] = ((const float4*)X)[base + j * 256];
#pragma unroll
        for (int j = 0; j < 4; j++) {
            __half2* o = (__half2*)(g_x + (base + j * 256) * 4);
            o[0] = __floats2half2_rn(v[j].x, v[j].y);
            o[1] = __floats2half2_rn(v[j].z, v[j].w);
        }
    } else if (id < 13056) {
        const int bid = id - 12544;
        const int w = bid >> 3, h = bid & 7;
        float* dst = g_bm + ((size_t)(w * NHD + h)) * 64 * 68;
        for (int idx = threadIdx.x; idx < 64 * 68; idx += 256) {
            int i = idx / 68, j = idx - i * 68;
            float v;
            if (j >= NTOK)      v = -1e30f;
            else if (i >= NTOK) v = 0.f;
            else {
                int ih = i / 7, iw = i - ih * 7;
                int jh = j / 7, jw = j - jh * 7;
                int r = (ih - jh + 6) * 13 + (iw - jw + 6);
                v = (mask[((size_t)w * NTOK + i) * NTOK + j] + table[r * NHD + h])
                    * LOG2E;
            }
            dst[idx] = v;
        }
    } else {
        const int wid = id - 13056;
        const int mat = wid >> 8, k = wid & 255, n = threadIdx.x;
        const float* W = (mat == 0) ? wq : (mat == 1) ? wk : wv;
        g_w[((size_t)mat * 256 + n) * 256 + k] = __float2half_rn(W[k * 256 + n]);
    }
}

// ---------------------------------------------------------------------------
// Kernel A: QKV projection (round-9 config; measured 262us — the legacy-HMMA
// issue roofline; mainloop frozen). Q scale folds in LOG2E (exp2 softmax).
// ---------------------------------------------------------------------------
#define QKV_SMEM 73728

__global__ __launch_bounds__(256, 2) void qkv_kernel(
    const float* __restrict__ bq, const float* __restrict__ bk,
    const float* __restrict__ bv)
{
    extern __shared__ __half sm[];   // stage s: As at s*18432, Bs at +9216 (halves)

    const int bx = blockIdx.x, by = blockIdx.y;
    const int tid = threadIdx.x;
    const int warp = tid >> 5, lane = tid & 31;
    const int wm = warp & 1, wn = warp >> 1;
    const int g = lane >> 2, tig = lane & 3;

    const int mat   = bx >> 1;
    const int ncol0 = (bx & 1) * 128;
    const float* bias = (mat == 0) ? bq : (mat == 1) ? bk : bv;

    const __half* xrow  = g_x + (size_t)by * 128 * 256;
    const __half* wbase = g_w + ((size_t)mat * 256 + ncol0) * 256;

    auto loadStage = [&](int s, int kp) {
        __half* A = sm + s * 18432;
        __half* B = sm + s * 18432 + 9216;
        const __half* xs = xrow + kp * 64;
        const __half* ws = wbase + kp * 64;
#pragma unroll
        for (int c = tid; c < 1024; c += 256) {
            int r = c >> 3, off = (c & 7) * 8;
            cp16(A + r * 72 + off, xs + (size_t)r * 256 + off);
        }
#pragma unroll
        for (int c = tid; c < 1024; c += 256) {
            int r = c >> 3, off = (c & 7) * 8;
            cp16(B + r * 72 + off, ws + (size_t)r * 256 + off);
        }
        asm volatile("cp.async.commit_group;" ::: "memory");
    };

    loadStage(0, 0);
    loadStage(1, 1);

    float acc[4][4][4];
#pragma unroll
    for (int mt = 0; mt < 4; mt++)
#pragma unroll
        for (int nt = 0; nt < 4; nt++)
#pragma unroll
            for (int e = 0; e < 4; e++) acc[mt][nt][e] = 0.f;

    const int aRow = wm * 64 + (lane & 15);
    const int aCol = (lane & 16) >> 1;
    const int bRow = wn * 32 + (lane & 7) + ((lane & 16) >> 1);
    const int bCol = lane & 8;

#pragma unroll
    for (int kp = 0; kp < 4; kp++) {
        if (kp < 3) asm volatile("cp.async.wait_group 1;" ::: "memory");
        else        asm volatile("cp.async.wait_group 0;" ::: "memory");
        __syncthreads();

        const __half* A = sm + (kp & 1) * 18432;
        const __half* B = sm + (kp & 1) * 18432 + 9216;

#pragma unroll
        for (int ks = 0; ks < 4; ks++) {
            const int kc = ks * 16;
            uint32_t bf0[4], bf1[4];
            ldsm4(bf0, B + bRow * 72 + kc + bCol);
            ldsm4(bf1, B + (bRow + 16) * 72 + kc + bCol);
#pragma unroll
            for (int mt = 0; mt < 4; mt++) {
                uint32_t a[4];
                ldsm4(a, A + (aRow + mt * 16) * 72 + kc + aCol);
                mma16816(acc[mt][0], a[0], a[1], a[2], a[3], bf0[0], bf0[1]);
                mma16816(acc[mt][1], a[0], a[1], a[2], a[3], bf0[2], bf0[3]);
                mma16816(acc[mt][2], a[0], a[1], a[2], a[3], bf1[0], bf1[1]);
                mma16816(acc[mt][3], a[0], a[1], a[2], a[3], bf1[2], bf1[3]);
            }
        }

        if (kp < 2) {
            __syncthreads();
            loadStage(kp & 1, kp + 2);
        }
    }

    __half* outp = (mat == 0) ? g_q : (mat == 1) ? g_k : g_v;
    const float scale = (mat == 0) ? 0.17677669529663687f * LOG2E : 1.0f;
#pragma unroll
    for (int mt = 0; mt < 4; mt++) {
#pragma unroll
        for (int hf = 0; hf < 2; hf++) {
            int m = by * 128 + wm * 64 + mt * 16 + g + hf * 8;
            int b = m / NTOK, n = m - b * NTOK;
#pragma unroll
            for (int nt = 0; nt < 4; nt++) {
                int c = ncol0 + wn * 32 + nt * 8 + 2 * tig;
                int h = c >> 5, d = c & 31;
                float v0 = (acc[mt][nt][hf * 2 + 0] + bias[c]) * scale;
                float v1 = (acc[mt][nt][hf * 2 + 1] + bias[c + 1]) * scale;
                *(__half2*)(outp + ((((size_t)b * NHD + h) * NTOK + n) * HDIM + d)) =
                    __floats2half2_rn(v0, v1);
            }
        }
    }
}

// ---------------------------------------------------------------------------
// Kernel B: windowed attention, 8 windows per CTA sharing one bm tile.
// 2 CTAs/SM (128 regs, no spills). Softmax via packed ex2.approx.f16x2
// (halves the MUFU load; result IS the P fragment). Direct gmem stores.
// ---------------------------------------------------------------------------
#define WINBUF    15360    // Qs 5120 + Ks 5120 + Vs 5120
#define ATTN_SMEM 77824    // 2*2*15360 + 64*64*4

__global__ __launch_bounds__(256, 2) void attn_kernel(float* __restrict__ out)
{
    extern __shared__ char smraw[];

    const int b0 = blockIdx.x;          // 0..511
    const int h  = blockIdx.y;
    const int w  = b0 & (NWIN - 1);

    const int tid = threadIdx.x;
    const int warp = tid >> 5, lane = tid & 31;
    const int half = warp >> 2;
    const int wl   = warp & 3;
    const int ht   = tid & 127;
    const int g = lane >> 2, tig = lane & 3;
    const int m0 = wl * 16;

    float* bmS = (float*)(smraw + 61440);   // 64 rows x 64 floats, swizzled
    const float* bm = g_bm + ((size_t)(w * NHD + h)) * 64 * 68;

    auto loadWin = [&](int s, int it) {
        const int b = b0 + 512 * (2 * it + half);
        const size_t base = ((size_t)b * NHD + h) * (NTOK * HDIM);
        char* hb = smraw + s * 30720 + half * WINBUF;
        __half (*Qs)[40] = (__half(*)[40])(hb);
        __half (*Ks)[40] = (__half(*)[40])(hb + 5120);
        __half (*Vs)[40] = (__half(*)[40])(hb + 10240);
        const __half* qp = g_q + base;
        const __half* kp = g_k + base;
        const __half* vp = g_v + base;
#pragma unroll
        for (int c = ht; c < 256; c += 128) {
            int r = c >> 2, off = (c & 3) * 8;
            cp16(&Qs[r][off], qp + r * 32 + off);
        }
#pragma unroll
        for (int c = ht; c < 256; c += 128) {
            int r = c >> 2, off = (c & 3) * 8;
            cp16(&Ks[r][off], kp + r * 32 + off);
        }
#pragma unroll
        for (int c = ht; c < 256; c += 128) {
            int r = c >> 2, off = (c & 3) * 8;
            cp16(&Vs[r][off], vp + r * 32 + off);
        }
    };

    // Prologue: bm (swizzled copy of cols 0..63) + stage0; then stage1.
    for (int c = tid; c < 1024; c += 256) {
        int i = c >> 4, c4 = (c & 15) * 4;
        int dst = i * 64 + ((c4 + 4 * i) & 63);
        cp16((char*)(bmS + dst), (const char*)(bm + i * 68 + c4));
    }
    loadWin(0, 0);
    asm volatile("cp.async.commit_group;" ::: "memory");
    loadWin(1, 1);
    asm volatile("cp.async.commit_group;" ::: "memory");

#pragma unroll
    for (int it = 0; it < 4; it++) {
        if (it < 3) asm volatile("cp.async.wait_group 1;" ::: "memory");
        else        asm volatile("cp.async.wait_group 0;" ::: "memory");
        __syncthreads();

        const int s = it & 1;
        char* hb = smraw + s * 30720 + half * WINBUF;
        __half (*Qs)[40] = (__half(*)[40])(hb);
        __half (*Ks)[40] = (__half(*)[40])(hb + 5120);
        __half (*Vs)[40] = (__half(*)[40])(hb + 10240);

        // --- scores = Q @ K^T (64 rows x 56 key cols: 7 n-tiles) ---
        float sc[7][4];
#pragma unroll
        for (int nt = 0; nt < 7; nt++)
#pragma unroll
            for (int e = 0; e < 4; e++) sc[nt][e] = 0.f;

#pragma unroll
        for (int ks = 0; ks < 2; ks++) {
            const int kc = ks * 16;
            uint32_t a[4];
            ldsm4(a, &Qs[m0 + (lane & 15)][kc + ((lane & 16) >> 1)]);
#pragma unroll
            for (int t = 0; t < 4; t++) {
                uint32_t bk_[4];
                ldsm4(bk_, &Ks[t * 16 + (lane & 7) + ((lane & 16) >> 1)][kc + (lane & 8)]);
                mma16816(sc[2 * t], a[0], a[1], a[2], a[3], bk_[0], bk_[1]);
                if (2 * t + 1 < 7)
                    mma16816(sc[2 * t + 1], a[0], a[1], a[2], a[3], bk_[2], bk_[3]);
            }
        }

        const int i0 = m0 + g, i1 = i0 + 8;
#pragma unroll
        for (int nt = 0; nt < 7; nt++) {
            int jc = nt * 8 + 2 * tig;
            float2 v0 = *(const float2*)&bmS[i0 * 64 + ((jc + 4 * i0) & 63)];
            float2 v1 = *(const float2*)&bmS[i1 * 64 + ((jc + 4 * i1) & 63)];
            sc[nt][0] += v0.x; sc[nt][1] += v0.y;
            sc[nt][2] += v1.x; sc[nt][3] += v1.y;
        }

        // --- softmax in exp2 domain, packed f16x2 MUFU ---
        float mx0 = -1e30f, mx1 = -1e30f;
#pragma unroll
        for (int nt = 0; nt < 7; nt++) {
            mx0 = fmaxf(mx0, fmaxf(sc[nt][0], sc[nt][1]));
            mx1 = fmaxf(mx1, fmaxf(sc[nt][2], sc[nt][3]));
        }
        mx0 = fmaxf(mx0, __shfl_xor_sync(0xffffffffu, mx0, 1));
        mx0 = fmaxf(mx0, __shfl_xor_sync(0xffffffffu, mx0, 2));
        mx1 = fmaxf(mx1, __shfl_xor_sync(0xffffffffu, mx1, 1));
        mx1 = fmaxf(mx1, __shfl_xor_sync(0xffffffffu, mx1, 2));

        // pe[nt][0] = half2(exp2 of rows i0 pair), pe[nt][1] = rows i1 pair.
        uint32_t pe[7][2];
        float s0 = 0.f, s1 = 0.f;
#pragma unroll
        for (int nt = 0; nt < 7; nt++) {
            pe[nt][0] = ex2h2(sc[nt][0] - mx0, sc[nt][1] - mx0);
            pe[nt][1] = ex2h2(sc[nt][2] - mx1, sc[nt][3] - mx1);
            float2 f0 = __half22float2(*(__half2*)&pe[nt][0]);
            float2 f1 = __half22float2(*(__half2*)&pe[nt][1]);
            s0 += f0.x + f0.y;
            s1 += f1.x + f1.y;
        }
        s0 += __shfl_xor_sync(0xffffffffu, s0, 1);
        s0 += __shfl_xor_sync(0xffffffffu, s0, 2);
        s1 += __shfl_xor_sync(0xffffffffu, s1, 1);
        s1 += __shfl_xor_sync(0xffffffffu, s1, 2);
        const float r0 = 1.f / s0, r1 = 1.f / s1;

        // --- ctx = P @ V (P fragments already packed in pe) ---
        float o[4][4];
#pragma unroll
        for (int nt = 0; nt < 4; nt++)
#pragma unroll
            for (int e = 0; e < 4; e++) o[nt][e] = 0.f;

#pragma unroll
        for (int kt = 0; kt < 4; kt++) {
            const int kc = kt * 16;
            const uint32_t a0 = pe[2 * kt][0];
            const uint32_t a1 = pe[2 * kt][1];
            const uint32_t a2 = (2 * kt + 1 < 7) ? pe[2 * kt + 1][0] : 0u;
            const uint32_t a3 = (2 * kt + 1 < 7) ? pe[2 * kt + 1][1] : 0u;
            uint32_t bv0[4], bv1[4];
            ldsm4t(bv0, &Vs[kc + (lane & 15)][0  + ((lane & 16) >> 1)]);
            ldsm4t(bv1, &Vs[kc + (lane & 15)][16 + ((lane & 16) >> 1)]);
            mma16816(o[0], a0, a1, a2, a3, bv0[0], bv0[1]);
            mma16816(o[1], a0, a1, a2, a3, bv0[2], bv0[3]);
            mma16816(o[2], a0, a1, a2, a3, bv1[0], bv1[1]);
            mma16816(o[3], a0, a1, a2, a3, bv1[2], bv1[3]);
        }

        // All reads of stage s complete; refill with window it+2 FIRST so the
        // cp.asyncs overlap the output stores below.
        __syncthreads();
        if (it < 2) {
            loadWin(s, it + 2);
            asm volatile("cp.async.commit_group;" ::: "memory");
        }

        // --- direct global stores ---
        const int b = b0 + 512 * (2 * it + half);
        float* ob = out + (size_t)b * NTOK * DMODEL + h * HDIM;
#pragma unroll
        for (int nt = 0; nt < 4; nt++) {
            int d = nt * 8 + 2 * tig;
            if (i0 < NTOK)
                *(float2*)(ob + (size_t)i0 * DMODEL + d) =
                    make_float2(o[nt][0] * r0, o[nt][1] * r0);
            if (i1 < NTOK)
                *(float2*)(ob + (size_t)i1 * DMODEL + d) =
                    make_float2(o[nt][2] * r1, o[nt][3] * r1);
        }
    }
}

extern "C" void kernel_launch(void* const* d_in, const int* in_sizes, int n_in,
                              void* d_out, int out_size)
{
    (void)in_sizes; (void)n_in; (void)out_size;
    const float* hidden = (const float*)d_in[0];
    const float* amask  = (const float*)d_in[1];
    const float* wq     = (const float*)d_in[2];
    const float* bq     = (const float*)d_in[3];
    const float* wk     = (const float*)d_in[4];
    const float* bk     = (const float*)d_in[5];
    const float* wv     = (const float*)d_in[6];
    const float* bv     = (const float*)d_in[7];
    const float* table  = (const float*)d_in[8];
    float* out = (float*)d_out;

    cudaFuncSetAttribute(qkv_kernel, cudaFuncAttributeMaxDynamicSharedMemorySize,
                         QKV_SMEM);
    cudaFuncSetAttribute(attn_kernel, cudaFuncAttributeMaxDynamicSharedMemorySize,
                         ATTN_SMEM);

    prep_all<<<13824, 256>>>(hidden, amask, table, wq, wk, wv);
    qkv_kernel<<<dim3(6, 1568), 256, QKV_SMEM>>>(bq, bk, bv);
    attn_kernel<<<dim3(512, NHD), 256, ATTN_SMEM>>>(out);
}